// round 12
// baseline (speedup 1.0000x reference)
#include <cuda_runtime.h>
#include <cuda_fp16.h>
#include <math.h>
#include <stdint.h>

#define Bsz 4
#define Tt  1024
#define Dm  1024
#define Hh  16
#define HD  64
#define DE  64
#define NT  8
#define NR  64
#define NHH 4
#define NA  2

typedef __half half_t;

// ---------------- scratch (device globals; no allocation allowed) ----------------
__device__ float g_nodes [Bsz*Tt*Dm];
__device__ float g_values[Bsz*Tt*Dm];
__device__ float g_x1    [Bsz*Tt*Dm];
__device__ float g_ax    [Bsz*Hh*Tt];
__device__ float g_evt   [Bsz*Tt*128];   // [t][0:64]=events, [64:72]=tlog
__device__ float g_pn    [NR*DE];
__device__ float g_Y0    [Bsz*Tt*Dm];
__device__ float g_Y1    [Bsz*Tt*Dm];
__device__ float g_wA    [Bsz*Tt*NA];
__device__ float g_ent   [Bsz*Tt];
__device__ float g_hidden[Bsz*Tt*Dm];
__device__ float g_act   [Bsz*Tt*Dm];
// fp16 activations
__device__ half_t g_xh  [Bsz*Tt*Dm];
__device__ half_t g_aoh [Bsz*Tt*Dm];
__device__ half_t g_x1h [Bsz*Tt*Dm];
__device__ half_t g_acth[Bsz*Tt*Dm];
// fp16 transposed weights [N][K]
__device__ half_t g_wnt [Dm*Dm];
__device__ half_t g_wvt [Dm*Dm];
__device__ half_t g_wot [Dm*Dm];
__device__ half_t g_wa0t[Dm*Dm];
__device__ half_t g_wa1t[Dm*Dm];
__device__ half_t g_wgt [Dm*2048];
__device__ half_t g_wet [128*Dm];        // [0:64]=W_event^T, [64:72]=W_type^T, rest 0

// ---------------- small helpers ----------------
__device__ __forceinline__ float ex2(float x) {
    float r; asm("ex2.approx.f32 %0,%1;" : "=f"(r) : "f"(x)); return r;
}
__device__ __forceinline__ void mma_f16(float* c, const unsigned* a, const unsigned* b) {
    asm volatile(
        "mma.sync.aligned.m16n8k16.row.col.f32.f16.f16.f32 "
        "{%0,%1,%2,%3},{%4,%5,%6,%7},{%8,%9},{%0,%1,%2,%3};"
        : "+f"(c[0]), "+f"(c[1]), "+f"(c[2]), "+f"(c[3])
        : "r"(a[0]), "r"(a[1]), "r"(a[2]), "r"(a[3]), "r"(b[0]), "r"(b[1]));
}
__device__ __forceinline__ void ldmx4(unsigned& r0, unsigned& r1, unsigned& r2, unsigned& r3,
                                      unsigned addr) {
    asm volatile("ldmatrix.sync.aligned.m8n8.x4.shared.b16 {%0,%1,%2,%3}, [%4];"
                 : "=r"(r0), "=r"(r1), "=r"(r2), "=r"(r3) : "r"(addr));
}
__device__ __forceinline__ float sigpoly(float a) {
    float a2 = a * a;
    return 0.5f + a * (0.25f + a2 * (-0.02083333333f + a2 * 0.002083333333f));
}
__device__ __forceinline__ uint32_t smem_u32(const void* p) {
    uint32_t a;
    asm("{ .reg .u64 t; cvta.to.shared.u64 t, %1; cvt.u32.u64 %0, t; }" : "=r"(a) : "l"(p));
    return a;
}
__device__ __forceinline__ unsigned packh2(float a, float b) {
    __half2 h = __floats2half2_rn(a, b);
    return *(unsigned*)&h;
}
__device__ __forceinline__ void packsplit(float a, float b, unsigned& hi, unsigned& lo) {
    hi = packh2(a, b);
    __half2 h = *(__half2*)&hi;
    lo = packh2(a - __half2float(__low2half(h)), b - __half2float(__high2half(h)));
}

// ================= fp16 tensor-core GEMM with ldmatrix fragments =================
// modes: 0 plain; 1 +addMat + fp16 copy; 3 gate; 4 plain with row stride ldc.
#define HSTG 16384
#define HB_OFF 8192
#define HG_SMEM (3*HSTG)

__global__ void __launch_bounds__(256, 2) hgemm(
    const half_t* __restrict__ A, const half_t* __restrict__ A2,
    const half_t* __restrict__ B0, const half_t* __restrict__ B1,
    float* __restrict__ C0, float* __restrict__ C1, half_t* __restrict__ Ch,
    const float* __restrict__ addMat, const float* __restrict__ bias,
    const float* __restrict__ entv, const float* __restrict__ wlast,
    int Ktot, int mode, int nbx, int ldc)
{
    extern __shared__ char hsm[];
    const uint32_t smb = smem_u32(hsm);
    const int tid = threadIdx.x, lane = tid & 31, warp = tid >> 5;
    const int g = lane >> 2, tg = lane & 3;
    const int wr = warp >> 2, wc = warp & 3;
    const int mat = blockIdx.x / nbx, cb = blockIdx.x % nbx;
    const int row0 = blockIdx.y * 128, col0 = cb * 128;
    const half_t* B = mat ? B1 : B0;
    float* C = mat ? C1 : C0;

    float acc[4][4][4];
    #pragma unroll
    for (int mt = 0; mt < 4; mt++)
        #pragma unroll
        for (int nt = 0; nt < 4; nt++)
            #pragma unroll
            for (int i = 0; i < 4; i++) acc[mt][nt][i] = 0.f;

    unsigned A_pre[4];
    {
        int lane15 = lane & 15;
        unsigned klaneA = (lane & 16) ? 16u : 0u;
        #pragma unroll
        for (int mt = 0; mt < 4; mt++) {
            int row = wr*64 + mt*16 + lane15;
            unsigned swr = ((row >> 1) & 3) << 4;
            A_pre[mt] = (unsigned)(row*64) + (klaneA ^ swr);
        }
    }
    unsigned B_pre[2];
    {
        unsigned klaneB = (lane & 8) ? 16u : 0u;
        int nbase = wc*32 + ((lane & 16) ? 8 : 0) + (lane & 7);
        #pragma unroll
        for (int ntp = 0; ntp < 2; ntp++) {
            int n = nbase + ntp*16;
            unsigned swn = ((n >> 1) & 3) << 4;
            B_pre[ntp] = (unsigned)(HB_OFF + n*64) + (klaneB ^ swn);
        }
    }

    const int rc = tid >> 2, qc = tid & 3;
    const int ktiles = Ktot / 32;

#define HLOAD(kt, st) do {                                                         \
        int kb_ = (kt) * 32;                                                       \
        const half_t* As_; int ac_;                                                \
        if (kb_ < 1024) { As_ = A; ac_ = kb_; } else { As_ = A2; ac_ = kb_ - 1024; } \
        uint32_t ab_ = smb + (st)*HSTG;                                            \
        uint32_t bb_ = ab_ + HB_OFF;                                               \
        _Pragma("unroll")                                                          \
        for (int i_ = 0; i_ < 2; i_++) {                                           \
            int r_ = rc + i_*64;                                                   \
            uint32_t sw_ = (uint32_t)(((r_ >> 1) & 3) << 4);                       \
            uint32_t co_ = ((uint32_t)(qc*16)) ^ sw_;                              \
            asm volatile("cp.async.ca.shared.global [%0],[%1],16;"                 \
                :: "r"(ab_ + r_*64 + co_),                                         \
                   "l"(As_ + (size_t)(row0 + r_)*1024 + ac_ + qc*8));              \
            asm volatile("cp.async.ca.shared.global [%0],[%1],16;"                 \
                :: "r"(bb_ + r_*64 + co_),                                         \
                   "l"(B + (size_t)(col0 + r_)*Ktot + kb_ + qc*8));                \
        }                                                                          \
        asm volatile("cp.async.commit_group;");                                    \
    } while (0)

    HLOAD(0, 0);
    HLOAD(1, 1);
    HLOAD(2, 2);

    for (int kt = 0; kt < ktiles; kt++) {
        int st = kt % 3;
        if (kt + 2 < ktiles)      asm volatile("cp.async.wait_group 2;");
        else if (kt + 1 < ktiles) asm volatile("cp.async.wait_group 1;");
        else                      asm volatile("cp.async.wait_group 0;");
        __syncthreads();

        const unsigned sbu = smb + st*HSTG;
        #pragma unroll
        for (unsigned kx = 0; kx < 64; kx += 32) {
            unsigned af[4][4], bfr[4][2];
            #pragma unroll
            for (int mt = 0; mt < 4; mt++)
                ldmx4(af[mt][0], af[mt][1], af[mt][2], af[mt][3],
                      sbu + (A_pre[mt] ^ kx));
            #pragma unroll
            for (int ntp = 0; ntp < 2; ntp++)
                ldmx4(bfr[2*ntp][0], bfr[2*ntp][1], bfr[2*ntp+1][0], bfr[2*ntp+1][1],
                      sbu + (B_pre[ntp] ^ kx));
            #pragma unroll
            for (int mt = 0; mt < 4; mt++)
                #pragma unroll
                for (int nt = 0; nt < 4; nt++)
                    mma_f16(acc[mt][nt], af[mt], bfr[nt]);
        }
        __syncthreads();
        if (kt + 3 < ktiles) HLOAD(kt + 3, st);
    }
#undef HLOAD

    #pragma unroll
    for (int mt = 0; mt < 4; mt++) {
        int r = row0 + wr*64 + mt*16 + g;
        float e0v = 0.f, e1v = 0.f;
        if (mode == 3) { e0v = entv[r]; e1v = entv[r + 8]; }
        #pragma unroll
        for (int nt = 0; nt < 4; nt++) {
            int c = col0 + wc*32 + nt*8 + 2*tg;
            float2 v0 = make_float2(acc[mt][nt][0], acc[mt][nt][1]);
            float2 v1 = make_float2(acc[mt][nt][2], acc[mt][nt][3]);
            if (mode == 1) {
                float2 a0 = *(const float2*)&addMat[(size_t)r * 1024 + c];
                float2 a1 = *(const float2*)&addMat[(size_t)(r + 8) * 1024 + c];
                v0.x += a0.x; v0.y += a0.y; v1.x += a1.x; v1.y += a1.y;
            } else if (mode == 3) {
                float2 bb = *(const float2*)&bias[c];
                float2 wl = *(const float2*)&wlast[c];
                v0.x += bb.x + e0v * wl.x; v0.y += bb.y + e0v * wl.y;
                v1.x += bb.x + e1v * wl.x; v1.y += bb.y + e1v * wl.y;
                v0.x = v0.x / (1.f + __expf(-v0.x));
                v0.y = v0.y / (1.f + __expf(-v0.y));
                v1.x = v1.x / (1.f + __expf(-v1.x));
                v1.y = v1.y / (1.f + __expf(-v1.y));
            }
            *(float2*)&C[(size_t)r * ldc + c] = v0;
            *(float2*)&C[(size_t)(r + 8) * ldc + c] = v1;
            if (mode == 1) {
                *(unsigned*)(Ch + (size_t)r * 1024 + c)       = packh2(v0.x, v0.y);
                *(unsigned*)(Ch + (size_t)(r + 8) * 1024 + c) = packh2(v1.x, v1.y);
            }
        }
    }
}

// ---------------- fp32 -> fp16 convert ----------------
__global__ void to_half(const float* __restrict__ X, half_t* __restrict__ H, int n2)
{
    for (int i = blockIdx.x * blockDim.x + threadIdx.x; i < n2; i += gridDim.x * blockDim.x) {
        float2 v = ((const float2*)X)[i];
        ((unsigned*)H)[i] = packh2(v.x, v.y);
    }
}

// ---------------- all weight transposes in one launch ----------------
__global__ void wtrans_all(
    const float* __restrict__ wn, const float* __restrict__ wv, const float* __restrict__ wo,
    const float* __restrict__ wa, const float* __restrict__ wg,
    const float* __restrict__ we, const float* __restrict__ wt,
    half_t* __restrict__ tn, half_t* __restrict__ tv, half_t* __restrict__ to2,
    half_t* __restrict__ ta0, half_t* __restrict__ ta1, half_t* __restrict__ tg2,
    half_t* __restrict__ te)
{
    __shared__ float t[32][33];
    const int z = blockIdx.z;
    int tx = threadIdx.x, ty = threadIdx.y;
    int k0 = blockIdx.y * 32, n0 = blockIdx.x * 32;

    if (z == 6) {
        // combined event|type weights -> te[128][1024]
        if (n0 >= 128 || k0 >= 1024) return;
        #pragma unroll
        for (int i = 0; i < 4; i++) {
            int kk = k0 + ty + 8*i;
            int col = n0 + tx;
            float v;
            if (col < 64)       v = we[(size_t)kk * 64 + col];
            else if (col < 72)  v = wt[(size_t)kk * 8 + (col - 64)];
            else                v = 0.f;
            t[ty + 8*i][tx] = v;
        }
        __syncthreads();
        #pragma unroll
        for (int i = 0; i < 4; i++) {
            int nn = ty + 8*i, kk = tx;
            te[(size_t)(n0 + nn) * 1024 + k0 + kk] = __float2half(t[kk][nn]);
        }
        return;
    }

    const float* W; half_t* T; int K = 1024;
    if      (z == 0) { W = wn; T = tn; }
    else if (z == 1) { W = wv; T = tv; }
    else if (z == 2) { W = wo; T = to2; }
    else if (z == 3) { W = wa; T = ta0; }
    else if (z == 4) { W = wa + 1024*1024; T = ta1; }
    else             { W = wg; T = tg2; K = 2048; }
    if (k0 >= K) return;
    #pragma unroll
    for (int i = 0; i < 4; i++)
        t[ty + 8*i][tx] = W[(size_t)(k0 + ty + 8*i) * 1024 + n0 + tx];
    __syncthreads();
    #pragma unroll
    for (int i = 0; i < 4; i++) {
        int nn = ty + 8*i, kk = tx;
        T[(size_t)(n0 + nn) * K + k0 + kk] = __float2half(t[kk][nn]);
    }
}

// ---------------- ax: one warp per (b,h,t) row, coalesced ----------------
__global__ void ax_kernel(const float* __restrict__ nodes,
                          const float* __restrict__ arity_w,
                          float* __restrict__ ax)
{
    int gw = (blockIdx.x * blockDim.x + threadIdx.x) >> 5;
    int lane = threadIdx.x & 31;
    if (gw >= Bsz*Hh*Tt) return;
    int t = gw % Tt, h = (gw / Tt) % Hh, b = gw / (Tt*Hh);
    const float2* np = (const float2*)(nodes + (size_t)(b*Tt + t)*Dm + h*HD);
    const float2* w  = (const float2*)(arity_w + h*HD);
    float2 a = np[lane], ww = w[lane];
    float s = a.x*ww.x + a.y*ww.y;
    s += __shfl_xor_sync(0xffffffffu, s, 1);
    s += __shfl_xor_sync(0xffffffffu, s, 2);
    s += __shfl_xor_sync(0xffffffffu, s, 4);
    s += __shfl_xor_sync(0xffffffffu, s, 8);
    s += __shfl_xor_sync(0xffffffffu, s, 16);
    if (lane == 0) ax[gw] = s;
}

// ---------------- fp16 tensor-core flash attention ----------------
#define AKS 68
#define AKSB (64*AKS)
#define AVOFF (2*AKSB)
#define KHOFF 69632
#define VTOFF 78848
#define PHOFF 88064
#define PLOFF 106496
#define AXOFF 124928
#define ATTN_SMEM 125440

__global__ void __launch_bounds__(256) attn_tc(
    const float* __restrict__ nodes, const float* __restrict__ values,
    const float* __restrict__ ax, half_t* __restrict__ outh)
{
    extern __shared__ char smbuf[];
    float*  KS = (float*)smbuf;
    float*  VS = (float*)smbuf + AVOFF;
    half_t* KH = (half_t*)(smbuf + KHOFF);
    half_t* VT = (half_t*)(smbuf + VTOFF);
    float*  axs = (float*)(smbuf + AXOFF);

    const int tid = threadIdx.x, lane = tid & 31, warp = tid >> 5;
    const int g = lane >> 2, tg = lane & 3;
    const int qblk = blockIdx.x, h = blockIdx.y, b = blockIdx.z;

    const float* nb  = nodes  + (size_t)(b*Tt)*Dm + h*HD;
    const float* vb  = values + (size_t)(b*Tt)*Dm + h*HD;
    const float* axp = ax + (b*Hh + h)*Tt;
    const int t0 = qblk * 128;
    const int r0 = t0 + warp*16 + g;

    half_t* PHw = (half_t*)(smbuf + PHOFF) + warp * 16 * 72;
    half_t* PLw = (half_t*)(smbuf + PLOFF) + warp * 16 * 72;

    unsigned qfh[4][4], qfl[4][4];
    #pragma unroll
    for (int kb = 0; kb < 4; kb++) {
        const float* q0 = nb + (size_t)r0*Dm + kb*16;
        const float* q1 = nb + (size_t)(r0+8)*Dm + kb*16;
        packsplit(q0[2*tg],     q0[2*tg+1],     qfh[kb][0], qfl[kb][0]);
        packsplit(q1[2*tg],     q1[2*tg+1],     qfh[kb][1], qfl[kb][1]);
        packsplit(q0[8+2*tg],   q0[8+2*tg+1],   qfh[kb][2], qfl[kb][2]);
        packsplit(q1[8+2*tg],   q1[8+2*tg+1],   qfh[kb][3], qfl[kb][3]);
    }
    const float axt0 = axp[r0] * 0.125f;
    const float axt1 = axp[r0+8] * 0.125f;

    float oacc[8][4];
    #pragma unroll
    for (int nt = 0; nt < 8; nt++)
        #pragma unroll
        for (int i = 0; i < 4; i++) oacc[nt][i] = 0.f;
    float m2a = -1e30f, m2b = -1e30f, la = 0.f, lb = 0.f;
    const float SC2 = 0.125f * 1.44269504f;

    unsigned smb = (unsigned)__cvta_generic_to_shared(smbuf);

#define ALOAD(kvt, bf) do {                                                       \
        int s0_ = (kvt) * 64;                                                     \
        _Pragma("unroll")                                                         \
        for (int i = 0; i < 4; i++) {                                             \
            int e = tid + i*256;                                                  \
            int r_ = e >> 4, c_ = (e & 15) * 4;                                   \
            unsigned kdst = smb + ((bf)*AKSB + r_*AKS + c_)*4;                    \
            unsigned vdst = smb + (AVOFF + (bf)*AKSB + r_*AKS + c_)*4;            \
            asm volatile("cp.async.ca.shared.global [%0],[%1],16;"                \
                :: "r"(kdst), "l"(nb + (size_t)(s0_+r_)*Dm + c_));                \
            asm volatile("cp.async.ca.shared.global [%0],[%1],16;"                \
                :: "r"(vdst), "l"(vb + (size_t)(s0_+r_)*Dm + c_));                \
        }                                                                         \
        if (tid < 16) {                                                           \
            unsigned adst = smb + AXOFF + ((bf)*64 + tid*4)*4;                    \
            asm volatile("cp.async.ca.shared.global [%0],[%1],16;"                \
                :: "r"(adst), "l"(axp + s0_ + tid*4));                            \
        }                                                                         \
        asm volatile("cp.async.commit_group;");                                   \
    } while (0)

    int buf = 0;
    ALOAD(0, 0);
    for (int kvt = 0; kvt < 16; kvt++) {
        if (kvt + 1 < 16) {
            ALOAD(kvt + 1, buf ^ 1);
            asm volatile("cp.async.wait_group 1;");
        } else {
            asm volatile("cp.async.wait_group 0;");
        }
        __syncthreads();

        #pragma unroll
        for (int i = 0; i < 4; i++) {
            int e = tid + i*256;
            int r_ = e >> 4, c_ = (e & 15) * 4;
            float4 k4 = *(const float4*)&KS[buf*AKSB + r_*AKS + c_];
            *(unsigned*)(KH + r_*72 + c_)     = packh2(k4.x, k4.y);
            *(unsigned*)(KH + r_*72 + c_ + 2) = packh2(k4.z, k4.w);
        }
        #pragma unroll
        for (int i = 0; i < 8; i++) {
            int e = tid + i*256;
            int d_ = e & 63, sp = e >> 6;
            float v0 = VS[buf*AKSB + (2*sp)*AKS + d_];
            float v1 = VS[buf*AKSB + (2*sp+1)*AKS + d_];
            *(unsigned*)(VT + d_*72 + 2*sp) = packh2(v0, v1);
        }
        __syncthreads();

        float sacc[8][4];
        #pragma unroll
        for (int nt = 0; nt < 8; nt++)
            #pragma unroll
            for (int i = 0; i < 4; i++) sacc[nt][i] = 0.f;
        #pragma unroll
        for (int kb = 0; kb < 4; kb++) {
            #pragma unroll
            for (int nt = 0; nt < 8; nt++) {
                const half_t* kr = KH + (nt*8 + g)*72 + kb*16;
                unsigned bfr[2];
                bfr[0] = *(const unsigned*)(kr + 2*tg);
                bfr[1] = *(const unsigned*)(kr + 8 + 2*tg);
                mma_f16(sacc[nt], qfh[kb], bfr);
                mma_f16(sacc[nt], qfl[kb], bfr);
            }
        }

        float tm0 = -1e30f, tm1 = -1e30f;
        #pragma unroll
        for (int nt = 0; nt < 8; nt++) {
            float ax0 = axs[buf*64 + nt*8 + 2*tg] * 0.125f;
            float ax1 = axs[buf*64 + nt*8 + 2*tg + 1] * 0.125f;
            sacc[nt][0] *= sigpoly(axt0 + ax0) * SC2;
            sacc[nt][1] *= sigpoly(axt0 + ax1) * SC2;
            sacc[nt][2] *= sigpoly(axt1 + ax0) * SC2;
            sacc[nt][3] *= sigpoly(axt1 + ax1) * SC2;
            tm0 = fmaxf(tm0, fmaxf(sacc[nt][0], sacc[nt][1]));
            tm1 = fmaxf(tm1, fmaxf(sacc[nt][2], sacc[nt][3]));
        }
        tm0 = fmaxf(tm0, __shfl_xor_sync(0xffffffffu, tm0, 1));
        tm0 = fmaxf(tm0, __shfl_xor_sync(0xffffffffu, tm0, 2));
        tm1 = fmaxf(tm1, __shfl_xor_sync(0xffffffffu, tm1, 1));
        tm1 = fmaxf(tm1, __shfl_xor_sync(0xffffffffu, tm1, 2));

        float mn0 = fmaxf(m2a, tm0), mn1 = fmaxf(m2b, tm1);
        float cr0 = ex2(m2a - mn0), cr1 = ex2(m2b - mn1);
        la *= cr0; lb *= cr1;
        #pragma unroll
        for (int nt = 0; nt < 8; nt++) {
            oacc[nt][0] *= cr0; oacc[nt][1] *= cr0;
            oacc[nt][2] *= cr1; oacc[nt][3] *= cr1;
        }
        m2a = mn0; m2b = mn1;

        #pragma unroll
        for (int nt = 0; nt < 8; nt++) {
            float p00 = ex2(sacc[nt][0] - mn0);
            float p01 = ex2(sacc[nt][1] - mn0);
            float p10 = ex2(sacc[nt][2] - mn1);
            float p11 = ex2(sacc[nt][3] - mn1);
            la += p00 + p01; lb += p10 + p11;
            unsigned h0, l0, h1, l1;
            packsplit(p00, p01, h0, l0);
            packsplit(p10, p11, h1, l1);
            *(unsigned*)(PHw + g*72 + nt*8 + 2*tg)     = h0;
            *(unsigned*)(PLw + g*72 + nt*8 + 2*tg)     = l0;
            *(unsigned*)(PHw + (g+8)*72 + nt*8 + 2*tg) = h1;
            *(unsigned*)(PLw + (g+8)*72 + nt*8 + 2*tg) = l1;
        }
        __syncwarp();

        #pragma unroll
        for (int kb = 0; kb < 4; kb++) {
            unsigned ph[4], pl[4];
            ph[0] = *(const unsigned*)(PHw + g*72 + kb*16 + 2*tg);
            ph[1] = *(const unsigned*)(PHw + (g+8)*72 + kb*16 + 2*tg);
            ph[2] = *(const unsigned*)(PHw + g*72 + kb*16 + 8 + 2*tg);
            ph[3] = *(const unsigned*)(PHw + (g+8)*72 + kb*16 + 8 + 2*tg);
            pl[0] = *(const unsigned*)(PLw + g*72 + kb*16 + 2*tg);
            pl[1] = *(const unsigned*)(PLw + (g+8)*72 + kb*16 + 2*tg);
            pl[2] = *(const unsigned*)(PLw + g*72 + kb*16 + 8 + 2*tg);
            pl[3] = *(const unsigned*)(PLw + (g+8)*72 + kb*16 + 8 + 2*tg);
            #pragma unroll
            for (int nt = 0; nt < 8; nt++) {
                const half_t* vr = VT + (nt*8 + g)*72 + kb*16;
                unsigned vf[2];
                vf[0] = *(const unsigned*)(vr + 2*tg);
                vf[1] = *(const unsigned*)(vr + 8 + 2*tg);
                mma_f16(oacc[nt], ph, vf);
                mma_f16(oacc[nt], pl, vf);
            }
        }
        __syncthreads();
        buf ^= 1;
    }
#undef ALOAD

    la += __shfl_xor_sync(0xffffffffu, la, 1);
    la += __shfl_xor_sync(0xffffffffu, la, 2);
    lb += __shfl_xor_sync(0xffffffffu, lb, 1);
    lb += __shfl_xor_sync(0xffffffffu, lb, 2);
    float i0 = 1.f / la, i1 = 1.f / lb;
    size_t o0 = (size_t)(b*Tt + r0)*Dm + h*HD;
    size_t o1 = (size_t)(b*Tt + r0 + 8)*Dm + h*HD;
    #pragma unroll
    for (int nt = 0; nt < 8; nt++) {
        *(unsigned*)(outh + o0 + nt*8 + 2*tg) = packh2(oacc[nt][0]*i0, oacc[nt][1]*i0);
        *(unsigned*)(outh + o1 + nt*8 + 2*tg) = packh2(oacc[nt][2]*i1, oacc[nt][3]*i1);
    }
}

// ---------------- normalized patterns ----------------
__global__ void pn_kernel(const float* __restrict__ patterns, float* __restrict__ pn)
{
    int r = threadIdx.x;
    float s = 0.f;
    #pragma unroll
    for (int d = 0; d < DE; d++) { float v = patterns[r*DE + d]; s += v*v; }
    float inv = 1.f / fmaxf(sqrtf(s), 1e-12f);
    #pragma unroll
    for (int d = 0; d < DE; d++) pn[r*DE + d] = patterns[r*DE + d] * inv;
}

// ---------------- per-token rule bank + entropy (reads evt[t][128]) ----------------
__global__ void token_kernel(
    const float* __restrict__ evt,
    const float* __restrict__ patterns, const float* __restrict__ pn,
    const float* __restrict__ W_alt, const float* __restrict__ log_temp,
    float* __restrict__ wA, float* __restrict__ entn)
{
    const int t = blockIdx.x;
    const int tid = threadIdx.x;
    __shared__ float en[64], sims[64], red[64], wp[64];
    __shared__ float sh_hw[4]; __shared__ int sh_idx[4];
    __shared__ float sh_misc[2];

    float e = evt[(size_t)t*128 + tid];
    red[tid] = e*e;
    __syncthreads();
    for (int off = 32; off > 0; off >>= 1) {
        if (tid < off) red[tid] += red[tid + off];
        __syncthreads();
    }
    float nrm = fmaxf(sqrtf(red[0]), 1e-12f);
    en[tid] = e / nrm;
    __syncthreads();

    float s = 0.f;
    #pragma unroll
    for (int d = 0; d < DE; d++) s += en[d] * pn[tid*DE + d];
    sims[tid] = s;
    __syncthreads();

    if (tid == 0) {
        float temp = expf(log_temp[0]);
        temp = fminf(fmaxf(temp, 0.01f), 10.f);
        float loc[NR];
        for (int r = 0; r < NR; r++) loc[r] = sims[r];
        float vals[NHH]; int idx[NHH];
        for (int k = 0; k < NHH; k++) {
            float best = -1e30f; int bi = 0;
            for (int r = 0; r < NR; r++)
                if (loc[r] > best) { best = loc[r]; bi = r; }
            vals[k] = best; idx[k] = bi; loc[bi] = -1e30f;
        }
        float sum = 0.f, w[NHH];
        for (int k = 0; k < NHH; k++) { w[k] = expf((vals[k] - vals[0]) / temp); sum += w[k]; }
        for (int k = 0; k < NHH; k++) { sh_hw[k] = w[k] / sum; sh_idx[k] = idx[k]; }
        sh_misc[0] = 1.f / (1.f + expf(-vals[0]));
        sh_misc[1] = temp;
    }
    __syncthreads();

    float wpv = 0.f;
    #pragma unroll
    for (int k = 0; k < NHH; k++) wpv += sh_hw[k] * patterns[sh_idx[k]*DE + tid];
    wp[tid] = wpv;
    __syncthreads();

    if (tid == 0) {
        float temp = sh_misc[1], sig = sh_misc[0];
        float l0 = 0.f, l1 = 0.f;
        for (int d = 0; d < DE; d++) { l0 += wp[d]*W_alt[d*NA]; l1 += wp[d]*W_alt[d*NA + 1]; }
        l0 /= temp; l1 /= temp;
        float mx = fmaxf(l0, l1);
        float e0 = expf(l0 - mx), e1 = expf(l1 - mx);
        float inv = 1.f / (e0 + e1);
        wA[t*NA]     = e0*inv*sig;
        wA[t*NA + 1] = e1*inv*sig;

        const float* tl = evt + (size_t)t*128 + 64;
        float m8 = -1e30f;
        for (int j = 0; j < NT; j++) m8 = fmaxf(m8, tl[j]);
        float se = 0.f, pz[NT];
        for (int j = 0; j < NT; j++) { pz[j] = expf(tl[j] - m8); se += pz[j]; }
        float ent = 0.f;
        for (int j = 0; j < NT; j++) {
            float p = pz[j] / se;
            ent -= p * logf(p + 1e-10f);
        }
        entn[t] = ent / logf((float)NT);
    }
}

// ---------------- combine: actions_out fp32 + fp16 ----------------
__global__ void combine_kernel(
    const float* __restrict__ Y0, const float* __restrict__ Y1,
    const float* __restrict__ wA,
    float* __restrict__ act, half_t* __restrict__ acth)
{
    const int t = blockIdx.x;
    const float w0 = wA[t*NA], w1 = wA[t*NA + 1];
    for (int c = threadIdx.x; c < Dm/2; c += blockDim.x) {
        size_t i = (size_t)t*(Dm/2) + c;
        float2 y0 = ((const float2*)Y0)[i];
        float2 y1 = ((const float2*)Y1)[i];
        float a0 = w0*y0.x + w1*y1.x;
        float a1 = w0*y0.y + w1*y1.y;
        ((float2*)act)[i] = make_float2(a0, a1);
        ((unsigned*)acth)[i] = packh2(a0, a1);
    }
}

// ---------------- gate scalar + final output ----------------
__global__ void final_kernel(
    const float* __restrict__ hidden, const float* __restrict__ Wg2,
    const float* __restrict__ bg2, const float* __restrict__ x1,
    const float* __restrict__ act, float* __restrict__ out)
{
    const int t = blockIdx.x;
    __shared__ float red[256];
    float s = 0.f;
    for (int c = threadIdx.x; c < Dm; c += 256)
        s += hidden[(size_t)t*Dm + c] * Wg2[c];
    red[threadIdx.x] = s;
    __syncthreads();
    for (int off = 128; off > 0; off >>= 1) {
        if (threadIdx.x < off) red[threadIdx.x] += red[threadIdx.x + off];
        __syncthreads();
    }
    float g = 1.f / (1.f + expf(-(red[0] + bg2[0])));
    for (int c = threadIdx.x; c < Dm; c += 256) {
        size_t i = (size_t)t*Dm + c;
        out[i] = x1[i] + g*act[i];
    }
}

// ---------------- host launcher ----------------
extern "C" void kernel_launch(void* const* d_in, const int* in_sizes, int n_in,
                              void* d_out, int out_size)
{
    const float* x        = (const float*)d_in[0];
    const float* W_node   = (const float*)d_in[1];
    const float* W_value  = (const float*)d_in[2];
    const float* W_out    = (const float*)d_in[3];
    const float* arity_w  = (const float*)d_in[4];
    const float* W_event  = (const float*)d_in[5];
    const float* W_type   = (const float*)d_in[6];
    const float* patterns = (const float*)d_in[7];
    const float* W_actions= (const float*)d_in[8];
    const float* W_alt    = (const float*)d_in[9];
    const float* log_temp = (const float*)d_in[10];
    const float* Wg1      = (const float*)d_in[11];
    const float* bg1      = (const float*)d_in[12];
    const float* Wg2      = (const float*)d_in[13];
    const float* bg2      = (const float*)d_in[14];
    float* out = (float*)d_out;

    float *nodes, *values, *x1, *ax, *evt, *pn, *Y0, *Y1, *wA, *ent, *hidden, *act;
    half_t *xh, *aoh, *x1h, *acth, *wnt, *wvt, *wot, *wa0t, *wa1t, *wgt, *wet;
    cudaGetSymbolAddress((void**)&nodes,  g_nodes);
    cudaGetSymbolAddress((void**)&values, g_values);
    cudaGetSymbolAddress((void**)&x1,     g_x1);
    cudaGetSymbolAddress((void**)&ax,     g_ax);
    cudaGetSymbolAddress((void**)&evt,    g_evt);
    cudaGetSymbolAddress((void**)&pn,     g_pn);
    cudaGetSymbolAddress((void**)&Y0,     g_Y0);
    cudaGetSymbolAddress((void**)&Y1,     g_Y1);
    cudaGetSymbolAddress((void**)&wA,     g_wA);
    cudaGetSymbolAddress((void**)&ent,    g_ent);
    cudaGetSymbolAddress((void**)&hidden, g_hidden);
    cudaGetSymbolAddress((void**)&act,    g_act);
    cudaGetSymbolAddress((void**)&xh,   g_xh);
    cudaGetSymbolAddress((void**)&aoh,  g_aoh);
    cudaGetSymbolAddress((void**)&x1h,  g_x1h);
    cudaGetSymbolAddress((void**)&acth, g_acth);
    cudaGetSymbolAddress((void**)&wnt,  g_wnt);
    cudaGetSymbolAddress((void**)&wvt,  g_wvt);
    cudaGetSymbolAddress((void**)&wot,  g_wot);
    cudaGetSymbolAddress((void**)&wa0t, g_wa0t);
    cudaGetSymbolAddress((void**)&wa1t, g_wa1t);
    cudaGetSymbolAddress((void**)&wgt,  g_wgt);
    cudaGetSymbolAddress((void**)&wet,  g_wet);

    cudaFuncSetAttribute(attn_tc, cudaFuncAttributeMaxDynamicSharedMemorySize, ATTN_SMEM);
    cudaFuncSetAttribute(hgemm,   cudaFuncAttributeMaxDynamicSharedMemorySize, HG_SMEM);

    const int M = Bsz*Tt;

    to_half<<<256, 256>>>(x, xh, M*Dm/2);
    wtrans_all<<<dim3(32, 64, 7), dim3(32, 8)>>>(W_node, W_value, W_out, W_actions, Wg1,
                                                 W_event, W_type,
                                                 wnt, wvt, wot, wa0t, wa1t, wgt, wet);

    // node | value
    hgemm<<<dim3(16, 32), 256, HG_SMEM>>>(xh, nullptr, wnt, wvt, nodes, values, nullptr,
        nullptr, nullptr, nullptr, nullptr, 1024, 0, 8, 1024);
    ax_kernel<<<(Bsz*Hh*Tt*32 + 255)/256, 256>>>(nodes, arity_w, ax);
    attn_tc<<<dim3(Tt/128, Hh, Bsz), 256, ATTN_SMEM>>>(nodes, values, ax, aoh);
    // x1 = x + attn_out @ W_out
    hgemm<<<dim3(8, 32), 256, HG_SMEM>>>(aoh, nullptr, wot, nullptr, x1, nullptr, x1h,
        x, nullptr, nullptr, nullptr, 1024, 1, 8, 1024);
    // events|tlog in one tensor GEMM (N=128 tile, ldc=128)
    hgemm<<<dim3(1, 32), 256, HG_SMEM>>>(x1h, nullptr, wet, nullptr, evt, nullptr, nullptr,
        nullptr, nullptr, nullptr, nullptr, 1024, 4, 1, 128);
    // Y0 | Y1
    hgemm<<<dim3(16, 32), 256, HG_SMEM>>>(x1h, nullptr, wa0t, wa1t, Y0, Y1, nullptr,
        nullptr, nullptr, nullptr, nullptr, 1024, 0, 8, 1024);
    pn_kernel<<<1, 64>>>(patterns, pn);
    token_kernel<<<M, 64>>>(evt, patterns, pn, W_alt, log_temp, wA, ent);
    combine_kernel<<<M, 256>>>(Y0, Y1, wA, act, acth);
    // gate
    hgemm<<<dim3(8, 32), 256, HG_SMEM>>>(x1h, acth, wgt, nullptr, hidden, nullptr, nullptr,
        nullptr, bg1, ent, Wg1 + (size_t)2048*1024, 2048, 3, 8, 1024);
    final_kernel<<<M, 256>>>(hidden, Wg2, bg2, x1, act, out);
}

// round 13
// speedup vs baseline: 1.5187x; 1.5187x over previous
#include <cuda_runtime.h>
#include <cuda_fp16.h>
#include <math.h>
#include <stdint.h>

#define Bsz 4
#define Tt  1024
#define Dm  1024
#define Hh  16
#define HD  64
#define DE  64
#define NT  8
#define NR  64
#define NHH 4
#define NA  2

typedef __half half_t;

// ---------------- scratch (device globals; no allocation allowed) ----------------
__device__ float g_nodes [Bsz*Tt*Dm];
__device__ float g_values[Bsz*Tt*Dm];
__device__ float g_x1    [Bsz*Tt*Dm];
__device__ float g_ax    [Bsz*Hh*Tt];
__device__ float g_evt   [Bsz*Tt*128];   // [t][0:64]=events, [64:72]=tlog
__device__ float g_pn    [NR*DE];
__device__ float g_Y0    [Bsz*Tt*Dm];
__device__ float g_Y1    [Bsz*Tt*Dm];
__device__ float g_wA    [Bsz*Tt*NA];
__device__ float g_ent   [Bsz*Tt];
__device__ float g_hidden[Bsz*Tt*Dm];
__device__ float g_act   [Bsz*Tt*Dm];
// fp16 activations
__device__ half_t g_xh  [Bsz*Tt*Dm];
__device__ half_t g_aoh [Bsz*Tt*Dm];
__device__ half_t g_x1h [Bsz*Tt*Dm];
__device__ half_t g_acth[Bsz*Tt*Dm];
// fp16 transposed weights [N][K]
__device__ half_t g_wnt [Dm*Dm];
__device__ half_t g_wvt [Dm*Dm];
__device__ half_t g_wot [Dm*Dm];
__device__ half_t g_wa0t[Dm*Dm];
__device__ half_t g_wa1t[Dm*Dm];
__device__ half_t g_wgt [Dm*2048];
__device__ half_t g_wet [128*Dm];        // [0:64]=W_event^T, [64:72]=W_type^T, rest 0

// ---------------- small helpers ----------------
__device__ __forceinline__ float ex2(float x) {
    float r; asm("ex2.approx.f32 %0,%1;" : "=f"(r) : "f"(x)); return r;
}
__device__ __forceinline__ void mma_f16(float* c, const unsigned* a, const unsigned* b) {
    asm volatile(
        "mma.sync.aligned.m16n8k16.row.col.f32.f16.f16.f32 "
        "{%0,%1,%2,%3},{%4,%5,%6,%7},{%8,%9},{%0,%1,%2,%3};"
        : "+f"(c[0]), "+f"(c[1]), "+f"(c[2]), "+f"(c[3])
        : "r"(a[0]), "r"(a[1]), "r"(a[2]), "r"(a[3]), "r"(b[0]), "r"(b[1]));
}
__device__ __forceinline__ void ldmx4(unsigned& r0, unsigned& r1, unsigned& r2, unsigned& r3,
                                      unsigned addr) {
    asm volatile("ldmatrix.sync.aligned.m8n8.x4.shared.b16 {%0,%1,%2,%3}, [%4];"
                 : "=r"(r0), "=r"(r1), "=r"(r2), "=r"(r3) : "r"(addr));
}
__device__ __forceinline__ float sigpoly(float a) {
    float a2 = a * a;
    return 0.5f + a * (0.25f + a2 * (-0.02083333333f + a2 * 0.002083333333f));
}
__device__ __forceinline__ uint32_t smem_u32(const void* p) {
    uint32_t a;
    asm("{ .reg .u64 t; cvta.to.shared.u64 t, %1; cvt.u32.u64 %0, t; }" : "=r"(a) : "l"(p));
    return a;
}
__device__ __forceinline__ unsigned packh2(float a, float b) {
    __half2 h = __floats2half2_rn(a, b);
    return *(unsigned*)&h;
}
__device__ __forceinline__ void packsplit(float a, float b, unsigned& hi, unsigned& lo) {
    hi = packh2(a, b);
    __half2 h = *(__half2*)&hi;
    lo = packh2(a - __half2float(__low2half(h)), b - __half2float(__high2half(h)));
}

// ================= fp16 tensor-core GEMM with ldmatrix fragments =================
// modes: 0 plain; 1 +addMat + fp16 copy; 3 gate; 4 plain with row stride ldc.
// occ 1 (NO minBlocks bound — occ=2 spills accumulators, measured +117us in R12).
#define HSTG 16384
#define HB_OFF 8192
#define HG_SMEM (3*HSTG)

__global__ void __launch_bounds__(256) hgemm(
    const half_t* __restrict__ A, const half_t* __restrict__ A2,
    const half_t* __restrict__ B0, const half_t* __restrict__ B1,
    float* __restrict__ C0, float* __restrict__ C1, half_t* __restrict__ Ch,
    const float* __restrict__ addMat, const float* __restrict__ bias,
    const float* __restrict__ entv, const float* __restrict__ wlast,
    int Ktot, int mode, int nbx, int ldc)
{
    extern __shared__ char hsm[];
    const uint32_t smb = smem_u32(hsm);
    const int tid = threadIdx.x, lane = tid & 31, warp = tid >> 5;
    const int g = lane >> 2, tg = lane & 3;
    const int wr = warp >> 2, wc = warp & 3;
    const int mat = blockIdx.x / nbx, cb = blockIdx.x % nbx;
    const int row0 = blockIdx.y * 128, col0 = cb * 128;
    const half_t* B = mat ? B1 : B0;
    float* C = mat ? C1 : C0;

    float acc[4][4][4];
    #pragma unroll
    for (int mt = 0; mt < 4; mt++)
        #pragma unroll
        for (int nt = 0; nt < 4; nt++)
            #pragma unroll
            for (int i = 0; i < 4; i++) acc[mt][nt][i] = 0.f;

    unsigned A_pre[4];
    {
        int lane15 = lane & 15;
        unsigned klaneA = (lane & 16) ? 16u : 0u;
        #pragma unroll
        for (int mt = 0; mt < 4; mt++) {
            int row = wr*64 + mt*16 + lane15;
            unsigned swr = ((row >> 1) & 3) << 4;
            A_pre[mt] = (unsigned)(row*64) + (klaneA ^ swr);
        }
    }
    unsigned B_pre[2];
    {
        unsigned klaneB = (lane & 8) ? 16u : 0u;
        int nbase = wc*32 + ((lane & 16) ? 8 : 0) + (lane & 7);
        #pragma unroll
        for (int ntp = 0; ntp < 2; ntp++) {
            int n = nbase + ntp*16;
            unsigned swn = ((n >> 1) & 3) << 4;
            B_pre[ntp] = (unsigned)(HB_OFF + n*64) + (klaneB ^ swn);
        }
    }

    const int rc = tid >> 2, qc = tid & 3;
    const int ktiles = Ktot / 32;

#define HLOAD(kt, st) do {                                                         \
        int kb_ = (kt) * 32;                                                       \
        const half_t* As_; int ac_;                                                \
        if (kb_ < 1024) { As_ = A; ac_ = kb_; } else { As_ = A2; ac_ = kb_ - 1024; } \
        uint32_t ab_ = smb + (st)*HSTG;                                            \
        uint32_t bb_ = ab_ + HB_OFF;                                               \
        _Pragma("unroll")                                                          \
        for (int i_ = 0; i_ < 2; i_++) {                                           \
            int r_ = rc + i_*64;                                                   \
            uint32_t sw_ = (uint32_t)(((r_ >> 1) & 3) << 4);                       \
            uint32_t co_ = ((uint32_t)(qc*16)) ^ sw_;                              \
            asm volatile("cp.async.ca.shared.global [%0],[%1],16;"                 \
                :: "r"(ab_ + r_*64 + co_),                                         \
                   "l"(As_ + (size_t)(row0 + r_)*1024 + ac_ + qc*8));              \
            asm volatile("cp.async.ca.shared.global [%0],[%1],16;"                 \
                :: "r"(bb_ + r_*64 + co_),                                         \
                   "l"(B + (size_t)(col0 + r_)*Ktot + kb_ + qc*8));                \
        }                                                                          \
        asm volatile("cp.async.commit_group;");                                    \
    } while (0)

    HLOAD(0, 0);
    HLOAD(1, 1);
    HLOAD(2, 2);

    for (int kt = 0; kt < ktiles; kt++) {
        int st = kt % 3;
        if (kt + 2 < ktiles)      asm volatile("cp.async.wait_group 2;");
        else if (kt + 1 < ktiles) asm volatile("cp.async.wait_group 1;");
        else                      asm volatile("cp.async.wait_group 0;");
        __syncthreads();

        const unsigned sbu = smb + st*HSTG;
        #pragma unroll
        for (unsigned kx = 0; kx < 64; kx += 32) {
            unsigned af[4][4], bfr[4][2];
            #pragma unroll
            for (int mt = 0; mt < 4; mt++)
                ldmx4(af[mt][0], af[mt][1], af[mt][2], af[mt][3],
                      sbu + (A_pre[mt] ^ kx));
            #pragma unroll
            for (int ntp = 0; ntp < 2; ntp++)
                ldmx4(bfr[2*ntp][0], bfr[2*ntp][1], bfr[2*ntp+1][0], bfr[2*ntp+1][1],
                      sbu + (B_pre[ntp] ^ kx));
            #pragma unroll
            for (int mt = 0; mt < 4; mt++)
                #pragma unroll
                for (int nt = 0; nt < 4; nt++)
                    mma_f16(acc[mt][nt], af[mt], bfr[nt]);
        }
        __syncthreads();
        if (kt + 3 < ktiles) HLOAD(kt + 3, st);
    }
#undef HLOAD

    #pragma unroll
    for (int mt = 0; mt < 4; mt++) {
        int r = row0 + wr*64 + mt*16 + g;
        float e0v = 0.f, e1v = 0.f;
        if (mode == 3) { e0v = entv[r]; e1v = entv[r + 8]; }
        #pragma unroll
        for (int nt = 0; nt < 4; nt++) {
            int c = col0 + wc*32 + nt*8 + 2*tg;
            float2 v0 = make_float2(acc[mt][nt][0], acc[mt][nt][1]);
            float2 v1 = make_float2(acc[mt][nt][2], acc[mt][nt][3]);
            if (mode == 1) {
                float2 a0 = *(const float2*)&addMat[(size_t)r * 1024 + c];
                float2 a1 = *(const float2*)&addMat[(size_t)(r + 8) * 1024 + c];
                v0.x += a0.x; v0.y += a0.y; v1.x += a1.x; v1.y += a1.y;
            } else if (mode == 3) {
                float2 bb = *(const float2*)&bias[c];
                float2 wl = *(const float2*)&wlast[c];
                v0.x += bb.x + e0v * wl.x; v0.y += bb.y + e0v * wl.y;
                v1.x += bb.x + e1v * wl.x; v1.y += bb.y + e1v * wl.y;
                v0.x = v0.x / (1.f + __expf(-v0.x));
                v0.y = v0.y / (1.f + __expf(-v0.y));
                v1.x = v1.x / (1.f + __expf(-v1.x));
                v1.y = v1.y / (1.f + __expf(-v1.y));
            }
            *(float2*)&C[(size_t)r * ldc + c] = v0;
            *(float2*)&C[(size_t)(r + 8) * ldc + c] = v1;
            if (mode == 1) {
                *(unsigned*)(Ch + (size_t)r * 1024 + c)       = packh2(v0.x, v0.y);
                *(unsigned*)(Ch + (size_t)(r + 8) * 1024 + c) = packh2(v1.x, v1.y);
            }
        }
    }
}

// ---------------- fp32 -> fp16 convert ----------------
__global__ void to_half(const float* __restrict__ X, half_t* __restrict__ H, int n2)
{
    for (int i = blockIdx.x * blockDim.x + threadIdx.x; i < n2; i += gridDim.x * blockDim.x) {
        float2 v = ((const float2*)X)[i];
        ((unsigned*)H)[i] = packh2(v.x, v.y);
    }
}

// ---------------- all weight transposes in one launch ----------------
__global__ void wtrans_all(
    const float* __restrict__ wn, const float* __restrict__ wv, const float* __restrict__ wo,
    const float* __restrict__ wa, const float* __restrict__ wg,
    const float* __restrict__ we, const float* __restrict__ wt,
    half_t* __restrict__ tn, half_t* __restrict__ tv, half_t* __restrict__ to2,
    half_t* __restrict__ ta0, half_t* __restrict__ ta1, half_t* __restrict__ tg2,
    half_t* __restrict__ te)
{
    __shared__ float t[32][33];
    const int z = blockIdx.z;
    int tx = threadIdx.x, ty = threadIdx.y;
    int k0 = blockIdx.y * 32, n0 = blockIdx.x * 32;

    if (z == 6) {
        if (n0 >= 128 || k0 >= 1024) return;
        #pragma unroll
        for (int i = 0; i < 4; i++) {
            int kk = k0 + ty + 8*i;
            int col = n0 + tx;
            float v;
            if (col < 64)       v = we[(size_t)kk * 64 + col];
            else if (col < 72)  v = wt[(size_t)kk * 8 + (col - 64)];
            else                v = 0.f;
            t[ty + 8*i][tx] = v;
        }
        __syncthreads();
        #pragma unroll
        for (int i = 0; i < 4; i++) {
            int nn = ty + 8*i, kk = tx;
            te[(size_t)(n0 + nn) * 1024 + k0 + kk] = __float2half(t[kk][nn]);
        }
        return;
    }

    const float* W; half_t* T; int K = 1024;
    if      (z == 0) { W = wn; T = tn; }
    else if (z == 1) { W = wv; T = tv; }
    else if (z == 2) { W = wo; T = to2; }
    else if (z == 3) { W = wa; T = ta0; }
    else if (z == 4) { W = wa + 1024*1024; T = ta1; }
    else             { W = wg; T = tg2; K = 2048; }
    if (k0 >= K) return;
    #pragma unroll
    for (int i = 0; i < 4; i++)
        t[ty + 8*i][tx] = W[(size_t)(k0 + ty + 8*i) * 1024 + n0 + tx];
    __syncthreads();
    #pragma unroll
    for (int i = 0; i < 4; i++) {
        int nn = ty + 8*i, kk = tx;
        T[(size_t)(n0 + nn) * K + k0 + kk] = __float2half(t[kk][nn]);
    }
}

// ---------------- ax: one warp per (b,h,t) row, coalesced ----------------
__global__ void ax_kernel(const float* __restrict__ nodes,
                          const float* __restrict__ arity_w,
                          float* __restrict__ ax)
{
    int gw = (blockIdx.x * blockDim.x + threadIdx.x) >> 5;
    int lane = threadIdx.x & 31;
    if (gw >= Bsz*Hh*Tt) return;
    int t = gw % Tt, h = (gw / Tt) % Hh, b = gw / (Tt*Hh);
    const float2* np = (const float2*)(nodes + (size_t)(b*Tt + t)*Dm + h*HD);
    const float2* w  = (const float2*)(arity_w + h*HD);
    float2 a = np[lane], ww = w[lane];
    float s = a.x*ww.x + a.y*ww.y;
    s += __shfl_xor_sync(0xffffffffu, s, 1);
    s += __shfl_xor_sync(0xffffffffu, s, 2);
    s += __shfl_xor_sync(0xffffffffu, s, 4);
    s += __shfl_xor_sync(0xffffffffu, s, 8);
    s += __shfl_xor_sync(0xffffffffu, s, 16);
    if (lane == 0) ax[gw] = s;
}

// ---------------- fp16 tensor-core flash attention ----------------
#define AKS 68
#define AKSB (64*AKS)
#define AVOFF (2*AKSB)
#define KHOFF 69632
#define VTOFF 78848
#define PHOFF 88064
#define PLOFF 106496
#define AXOFF 124928
#define ATTN_SMEM 125440

__global__ void __launch_bounds__(256) attn_tc(
    const float* __restrict__ nodes, const float* __restrict__ values,
    const float* __restrict__ ax, half_t* __restrict__ outh)
{
    extern __shared__ char smbuf[];
    float*  KS = (float*)smbuf;
    float*  VS = (float*)smbuf + AVOFF;
    half_t* KH = (half_t*)(smbuf + KHOFF);
    half_t* VT = (half_t*)(smbuf + VTOFF);
    float*  axs = (float*)(smbuf + AXOFF);

    const int tid = threadIdx.x, lane = tid & 31, warp = tid >> 5;
    const int g = lane >> 2, tg = lane & 3;
    const int qblk = blockIdx.x, h = blockIdx.y, b = blockIdx.z;

    const float* nb  = nodes  + (size_t)(b*Tt)*Dm + h*HD;
    const float* vb  = values + (size_t)(b*Tt)*Dm + h*HD;
    const float* axp = ax + (b*Hh + h)*Tt;
    const int t0 = qblk * 128;
    const int r0 = t0 + warp*16 + g;

    half_t* PHw = (half_t*)(smbuf + PHOFF) + warp * 16 * 72;
    half_t* PLw = (half_t*)(smbuf + PLOFF) + warp * 16 * 72;

    unsigned qfh[4][4], qfl[4][4];
    #pragma unroll
    for (int kb = 0; kb < 4; kb++) {
        const float* q0 = nb + (size_t)r0*Dm + kb*16;
        const float* q1 = nb + (size_t)(r0+8)*Dm + kb*16;
        packsplit(q0[2*tg],     q0[2*tg+1],     qfh[kb][0], qfl[kb][0]);
        packsplit(q1[2*tg],     q1[2*tg+1],     qfh[kb][1], qfl[kb][1]);
        packsplit(q0[8+2*tg],   q0[8+2*tg+1],   qfh[kb][2], qfl[kb][2]);
        packsplit(q1[8+2*tg],   q1[8+2*tg+1],   qfh[kb][3], qfl[kb][3]);
    }
    const float axt0 = axp[r0] * 0.125f;
    const float axt1 = axp[r0+8] * 0.125f;

    float oacc[8][4];
    #pragma unroll
    for (int nt = 0; nt < 8; nt++)
        #pragma unroll
        for (int i = 0; i < 4; i++) oacc[nt][i] = 0.f;
    float m2a = -1e30f, m2b = -1e30f, la = 0.f, lb = 0.f;
    const float SC2 = 0.125f * 1.44269504f;

    unsigned smb = (unsigned)__cvta_generic_to_shared(smbuf);

#define ALOAD(kvt, bf) do {                                                       \
        int s0_ = (kvt) * 64;                                                     \
        _Pragma("unroll")                                                         \
        for (int i = 0; i < 4; i++) {                                             \
            int e = tid + i*256;                                                  \
            int r_ = e >> 4, c_ = (e & 15) * 4;                                   \
            unsigned kdst = smb + ((bf)*AKSB + r_*AKS + c_)*4;                    \
            unsigned vdst = smb + (AVOFF + (bf)*AKSB + r_*AKS + c_)*4;            \
            asm volatile("cp.async.ca.shared.global [%0],[%1],16;"                \
                :: "r"(kdst), "l"(nb + (size_t)(s0_+r_)*Dm + c_));                \
            asm volatile("cp.async.ca.shared.global [%0],[%1],16;"                \
                :: "r"(vdst), "l"(vb + (size_t)(s0_+r_)*Dm + c_));                \
        }                                                                         \
        if (tid < 16) {                                                           \
            unsigned adst = smb + AXOFF + ((bf)*64 + tid*4)*4;                    \
            asm volatile("cp.async.ca.shared.global [%0],[%1],16;"                \
                :: "r"(adst), "l"(axp + s0_ + tid*4));                            \
        }                                                                         \
        asm volatile("cp.async.commit_group;");                                   \
    } while (0)

    int buf = 0;
    ALOAD(0, 0);
    for (int kvt = 0; kvt < 16; kvt++) {
        if (kvt + 1 < 16) {
            ALOAD(kvt + 1, buf ^ 1);
            asm volatile("cp.async.wait_group 1;");
        } else {
            asm volatile("cp.async.wait_group 0;");
        }
        __syncthreads();

        #pragma unroll
        for (int i = 0; i < 4; i++) {
            int e = tid + i*256;
            int r_ = e >> 4, c_ = (e & 15) * 4;
            float4 k4 = *(const float4*)&KS[buf*AKSB + r_*AKS + c_];
            *(unsigned*)(KH + r_*72 + c_)     = packh2(k4.x, k4.y);
            *(unsigned*)(KH + r_*72 + c_ + 2) = packh2(k4.z, k4.w);
        }
        #pragma unroll
        for (int i = 0; i < 8; i++) {
            int e = tid + i*256;
            int d_ = e & 63, sp = e >> 6;
            float v0 = VS[buf*AKSB + (2*sp)*AKS + d_];
            float v1 = VS[buf*AKSB + (2*sp+1)*AKS + d_];
            *(unsigned*)(VT + d_*72 + 2*sp) = packh2(v0, v1);
        }
        __syncthreads();

        float sacc[8][4];
        #pragma unroll
        for (int nt = 0; nt < 8; nt++)
            #pragma unroll
            for (int i = 0; i < 4; i++) sacc[nt][i] = 0.f;
        #pragma unroll
        for (int kb = 0; kb < 4; kb++) {
            #pragma unroll
            for (int nt = 0; nt < 8; nt++) {
                const half_t* kr = KH + (nt*8 + g)*72 + kb*16;
                unsigned bfr[2];
                bfr[0] = *(const unsigned*)(kr + 2*tg);
                bfr[1] = *(const unsigned*)(kr + 8 + 2*tg);
                mma_f16(sacc[nt], qfh[kb], bfr);
                mma_f16(sacc[nt], qfl[kb], bfr);
            }
        }

        float tm0 = -1e30f, tm1 = -1e30f;
        #pragma unroll
        for (int nt = 0; nt < 8; nt++) {
            float ax0 = axs[buf*64 + nt*8 + 2*tg] * 0.125f;
            float ax1 = axs[buf*64 + nt*8 + 2*tg + 1] * 0.125f;
            sacc[nt][0] *= sigpoly(axt0 + ax0) * SC2;
            sacc[nt][1] *= sigpoly(axt0 + ax1) * SC2;
            sacc[nt][2] *= sigpoly(axt1 + ax0) * SC2;
            sacc[nt][3] *= sigpoly(axt1 + ax1) * SC2;
            tm0 = fmaxf(tm0, fmaxf(sacc[nt][0], sacc[nt][1]));
            tm1 = fmaxf(tm1, fmaxf(sacc[nt][2], sacc[nt][3]));
        }
        tm0 = fmaxf(tm0, __shfl_xor_sync(0xffffffffu, tm0, 1));
        tm0 = fmaxf(tm0, __shfl_xor_sync(0xffffffffu, tm0, 2));
        tm1 = fmaxf(tm1, __shfl_xor_sync(0xffffffffu, tm1, 1));
        tm1 = fmaxf(tm1, __shfl_xor_sync(0xffffffffu, tm1, 2));

        float mn0 = fmaxf(m2a, tm0), mn1 = fmaxf(m2b, tm1);
        float cr0 = ex2(m2a - mn0), cr1 = ex2(m2b - mn1);
        la *= cr0; lb *= cr1;
        #pragma unroll
        for (int nt = 0; nt < 8; nt++) {
            oacc[nt][0] *= cr0; oacc[nt][1] *= cr0;
            oacc[nt][2] *= cr1; oacc[nt][3] *= cr1;
        }
        m2a = mn0; m2b = mn1;

        #pragma unroll
        for (int nt = 0; nt < 8; nt++) {
            float p00 = ex2(sacc[nt][0] - mn0);
            float p01 = ex2(sacc[nt][1] - mn0);
            float p10 = ex2(sacc[nt][2] - mn1);
            float p11 = ex2(sacc[nt][3] - mn1);
            la += p00 + p01; lb += p10 + p11;
            unsigned h0, l0, h1, l1;
            packsplit(p00, p01, h0, l0);
            packsplit(p10, p11, h1, l1);
            *(unsigned*)(PHw + g*72 + nt*8 + 2*tg)     = h0;
            *(unsigned*)(PLw + g*72 + nt*8 + 2*tg)     = l0;
            *(unsigned*)(PHw + (g+8)*72 + nt*8 + 2*tg) = h1;
            *(unsigned*)(PLw + (g+8)*72 + nt*8 + 2*tg) = l1;
        }
        __syncwarp();

        #pragma unroll
        for (int kb = 0; kb < 4; kb++) {
            unsigned ph[4], pl[4];
            ph[0] = *(const unsigned*)(PHw + g*72 + kb*16 + 2*tg);
            ph[1] = *(const unsigned*)(PHw + (g+8)*72 + kb*16 + 2*tg);
            ph[2] = *(const unsigned*)(PHw + g*72 + kb*16 + 8 + 2*tg);
            ph[3] = *(const unsigned*)(PHw + (g+8)*72 + kb*16 + 8 + 2*tg);
            pl[0] = *(const unsigned*)(PLw + g*72 + kb*16 + 2*tg);
            pl[1] = *(const unsigned*)(PLw + (g+8)*72 + kb*16 + 2*tg);
            pl[2] = *(const unsigned*)(PLw + g*72 + kb*16 + 8 + 2*tg);
            pl[3] = *(const unsigned*)(PLw + (g+8)*72 + kb*16 + 8 + 2*tg);
            #pragma unroll
            for (int nt = 0; nt < 8; nt++) {
                const half_t* vr = VT + (nt*8 + g)*72 + kb*16;
                unsigned vf[2];
                vf[0] = *(const unsigned*)(vr + 2*tg);
                vf[1] = *(const unsigned*)(vr + 8 + 2*tg);
                mma_f16(oacc[nt], ph, vf);
                mma_f16(oacc[nt], pl, vf);
            }
        }
        __syncthreads();
        buf ^= 1;
    }
#undef ALOAD

    la += __shfl_xor_sync(0xffffffffu, la, 1);
    la += __shfl_xor_sync(0xffffffffu, la, 2);
    lb += __shfl_xor_sync(0xffffffffu, lb, 1);
    lb += __shfl_xor_sync(0xffffffffu, lb, 2);
    float i0 = 1.f / la, i1 = 1.f / lb;
    size_t o0 = (size_t)(b*Tt + r0)*Dm + h*HD;
    size_t o1 = (size_t)(b*Tt + r0 + 8)*Dm + h*HD;
    #pragma unroll
    for (int nt = 0; nt < 8; nt++) {
        *(unsigned*)(outh + o0 + nt*8 + 2*tg) = packh2(oacc[nt][0]*i0, oacc[nt][1]*i0);
        *(unsigned*)(outh + o1 + nt*8 + 2*tg) = packh2(oacc[nt][2]*i1, oacc[nt][3]*i1);
    }
}

// ---------------- normalized patterns ----------------
__global__ void pn_kernel(const float* __restrict__ patterns, float* __restrict__ pn)
{
    int r = threadIdx.x;
    float s = 0.f;
    #pragma unroll
    for (int d = 0; d < DE; d++) { float v = patterns[r*DE + d]; s += v*v; }
    float inv = 1.f / fmaxf(sqrtf(s), 1e-12f);
    #pragma unroll
    for (int d = 0; d < DE; d++) pn[r*DE + d] = patterns[r*DE + d] * inv;
}

// ---------------- per-token rule bank + entropy (reads evt[t][128]) ----------------
__global__ void token_kernel(
    const float* __restrict__ evt,
    const float* __restrict__ patterns, const float* __restrict__ pn,
    const float* __restrict__ W_alt, const float* __restrict__ log_temp,
    float* __restrict__ wA, float* __restrict__ entn)
{
    const int t = blockIdx.x;
    const int tid = threadIdx.x;
    __shared__ float en[64], sims[64], red[64], wp[64];
    __shared__ float sh_hw[4]; __shared__ int sh_idx[4];
    __shared__ float sh_misc[2];

    float e = evt[(size_t)t*128 + tid];
    red[tid] = e*e;
    __syncthreads();
    for (int off = 32; off > 0; off >>= 1) {
        if (tid < off) red[tid] += red[tid + off];
        __syncthreads();
    }
    float nrm = fmaxf(sqrtf(red[0]), 1e-12f);
    en[tid] = e / nrm;
    __syncthreads();

    float s = 0.f;
    #pragma unroll
    for (int d = 0; d < DE; d++) s += en[d] * pn[tid*DE + d];
    sims[tid] = s;
    __syncthreads();

    if (tid == 0) {
        float temp = expf(log_temp[0]);
        temp = fminf(fmaxf(temp, 0.01f), 10.f);
        float loc[NR];
        for (int r = 0; r < NR; r++) loc[r] = sims[r];
        float vals[NHH]; int idx[NHH];
        for (int k = 0; k < NHH; k++) {
            float best = -1e30f; int bi = 0;
            for (int r = 0; r < NR; r++)
                if (loc[r] > best) { best = loc[r]; bi = r; }
            vals[k] = best; idx[k] = bi; loc[bi] = -1e30f;
        }
        float sum = 0.f, w[NHH];
        for (int k = 0; k < NHH; k++) { w[k] = expf((vals[k] - vals[0]) / temp); sum += w[k]; }
        for (int k = 0; k < NHH; k++) { sh_hw[k] = w[k] / sum; sh_idx[k] = idx[k]; }
        sh_misc[0] = 1.f / (1.f + expf(-vals[0]));
        sh_misc[1] = temp;
    }
    __syncthreads();

    float wpv = 0.f;
    #pragma unroll
    for (int k = 0; k < NHH; k++) wpv += sh_hw[k] * patterns[sh_idx[k]*DE + tid];
    wp[tid] = wpv;
    __syncthreads();

    if (tid == 0) {
        float temp = sh_misc[1], sig = sh_misc[0];
        float l0 = 0.f, l1 = 0.f;
        for (int d = 0; d < DE; d++) { l0 += wp[d]*W_alt[d*NA]; l1 += wp[d]*W_alt[d*NA + 1]; }
        l0 /= temp; l1 /= temp;
        float mx = fmaxf(l0, l1);
        float e0 = expf(l0 - mx), e1 = expf(l1 - mx);
        float inv = 1.f / (e0 + e1);
        wA[t*NA]     = e0*inv*sig;
        wA[t*NA + 1] = e1*inv*sig;

        const float* tl = evt + (size_t)t*128 + 64;
        float m8 = -1e30f;
        for (int j = 0; j < NT; j++) m8 = fmaxf(m8, tl[j]);
        float se = 0.f, pz[NT];
        for (int j = 0; j < NT; j++) { pz[j] = expf(tl[j] - m8); se += pz[j]; }
        float ent = 0.f;
        for (int j = 0; j < NT; j++) {
            float p = pz[j] / se;
            ent -= p * logf(p + 1e-10f);
        }
        entn[t] = ent / logf((float)NT);
    }
}

// ---------------- combine: actions_out fp32 + fp16 ----------------
__global__ void combine_kernel(
    const float* __restrict__ Y0, const float* __restrict__ Y1,
    const float* __restrict__ wA,
    float* __restrict__ act, half_t* __restrict__ acth)
{
    const int t = blockIdx.x;
    const float w0 = wA[t*NA], w1 = wA[t*NA + 1];
    for (int c = threadIdx.x; c < Dm/2; c += blockDim.x) {
        size_t i = (size_t)t*(Dm/2) + c;
        float2 y0 = ((const float2*)Y0)[i];
        float2 y1 = ((const float2*)Y1)[i];
        float a0 = w0*y0.x + w1*y1.x;
        float a1 = w0*y0.y + w1*y1.y;
        ((float2*)act)[i] = make_float2(a0, a1);
        ((unsigned*)acth)[i] = packh2(a0, a1);
    }
}

// ---------------- gate scalar + final output ----------------
__global__ void final_kernel(
    const float* __restrict__ hidden, const float* __restrict__ Wg2,
    const float* __restrict__ bg2, const float* __restrict__ x1,
    const float* __restrict__ act, float* __restrict__ out)
{
    const int t = blockIdx.x;
    __shared__ float red[256];
    float s = 0.f;
    for (int c = threadIdx.x; c < Dm; c += 256)
        s += hidden[(size_t)t*Dm + c] * Wg2[c];
    red[threadIdx.x] = s;
    __syncthreads();
    for (int off = 128; off > 0; off >>= 1) {
        if (threadIdx.x < off) red[threadIdx.x] += red[threadIdx.x + off];
        __syncthreads();
    }
    float g = 1.f / (1.f + expf(-(red[0] + bg2[0])));
    for (int c = threadIdx.x; c < Dm; c += 256) {
        size_t i = (size_t)t*Dm + c;
        out[i] = x1[i] + g*act[i];
    }
}

// ---------------- host launcher ----------------
extern "C" void kernel_launch(void* const* d_in, const int* in_sizes, int n_in,
                              void* d_out, int out_size)
{
    const float* x        = (const float*)d_in[0];
    const float* W_node   = (const float*)d_in[1];
    const float* W_value  = (const float*)d_in[2];
    const float* W_out    = (const float*)d_in[3];
    const float* arity_w  = (const float*)d_in[4];
    const float* W_event  = (const float*)d_in[5];
    const float* W_type   = (const float*)d_in[6];
    const float* patterns = (const float*)d_in[7];
    const float* W_actions= (const float*)d_in[8];
    const float* W_alt    = (const float*)d_in[9];
    const float* log_temp = (const float*)d_in[10];
    const float* Wg1      = (const float*)d_in[11];
    const float* bg1      = (const float*)d_in[12];
    const float* Wg2      = (const float*)d_in[13];
    const float* bg2      = (const float*)d_in[14];
    float* out = (float*)d_out;

    float *nodes, *values, *x1, *ax, *evt, *pn, *Y0, *Y1, *wA, *ent, *hidden, *act;
    half_t *xh, *aoh, *x1h, *acth, *wnt, *wvt, *wot, *wa0t, *wa1t, *wgt, *wet;
    cudaGetSymbolAddress((void**)&nodes,  g_nodes);
    cudaGetSymbolAddress((void**)&values, g_values);
    cudaGetSymbolAddress((void**)&x1,     g_x1);
    cudaGetSymbolAddress((void**)&ax,     g_ax);
    cudaGetSymbolAddress((void**)&evt,    g_evt);
    cudaGetSymbolAddress((void**)&pn,     g_pn);
    cudaGetSymbolAddress((void**)&Y0,     g_Y0);
    cudaGetSymbolAddress((void**)&Y1,     g_Y1);
    cudaGetSymbolAddress((void**)&wA,     g_wA);
    cudaGetSymbolAddress((void**)&ent,    g_ent);
    cudaGetSymbolAddress((void**)&hidden, g_hidden);
    cudaGetSymbolAddress((void**)&act,    g_act);
    cudaGetSymbolAddress((void**)&xh,   g_xh);
    cudaGetSymbolAddress((void**)&aoh,  g_aoh);
    cudaGetSymbolAddress((void**)&x1h,  g_x1h);
    cudaGetSymbolAddress((void**)&acth, g_acth);
    cudaGetSymbolAddress((void**)&wnt,  g_wnt);
    cudaGetSymbolAddress((void**)&wvt,  g_wvt);
    cudaGetSymbolAddress((void**)&wot,  g_wot);
    cudaGetSymbolAddress((void**)&wa0t, g_wa0t);
    cudaGetSymbolAddress((void**)&wa1t, g_wa1t);
    cudaGetSymbolAddress((void**)&wgt,  g_wgt);
    cudaGetSymbolAddress((void**)&wet,  g_wet);

    cudaFuncSetAttribute(attn_tc, cudaFuncAttributeMaxDynamicSharedMemorySize, ATTN_SMEM);
    cudaFuncSetAttribute(hgemm,   cudaFuncAttributeMaxDynamicSharedMemorySize, HG_SMEM);

    const int M = Bsz*Tt;

    to_half<<<256, 256>>>(x, xh, M*Dm/2);
    wtrans_all<<<dim3(32, 64, 7), dim3(32, 8)>>>(W_node, W_value, W_out, W_actions, Wg1,
                                                 W_event, W_type,
                                                 wnt, wvt, wot, wa0t, wa1t, wgt, wet);

    // node | value
    hgemm<<<dim3(16, 32), 256, HG_SMEM>>>(xh, nullptr, wnt, wvt, nodes, values, nullptr,
        nullptr, nullptr, nullptr, nullptr, 1024, 0, 8, 1024);
    ax_kernel<<<(Bsz*Hh*Tt*32 + 255)/256, 256>>>(nodes, arity_w, ax);
    attn_tc<<<dim3(Tt/128, Hh, Bsz), 256, ATTN_SMEM>>>(nodes, values, ax, aoh);
    // x1 = x + attn_out @ W_out
    hgemm<<<dim3(8, 32), 256, HG_SMEM>>>(aoh, nullptr, wot, nullptr, x1, nullptr, x1h,
        x, nullptr, nullptr, nullptr, 1024, 1, 8, 1024);
    // events|tlog in one tensor GEMM (N=128 tile, ldc=128)
    hgemm<<<dim3(1, 32), 256, HG_SMEM>>>(x1h, nullptr, wet, nullptr, evt, nullptr, nullptr,
        nullptr, nullptr, nullptr, nullptr, 1024, 4, 1, 128);
    // Y0 | Y1
    hgemm<<<dim3(16, 32), 256, HG_SMEM>>>(x1h, nullptr, wa0t, wa1t, Y0, Y1, nullptr,
        nullptr, nullptr, nullptr, nullptr, 1024, 0, 8, 1024);
    pn_kernel<<<1, 64>>>(patterns, pn);
    token_kernel<<<M, 64>>>(evt, patterns, pn, W_alt, log_temp, wA, ent);
    combine_kernel<<<M, 256>>>(Y0, Y1, wA, act, acth);
    // gate
    hgemm<<<dim3(8, 32), 256, HG_SMEM>>>(x1h, acth, wgt, nullptr, hidden, nullptr, nullptr,
        nullptr, bg1, ent, Wg1 + (size_t)2048*1024, 2048, 3, 8, 1024);
    final_kernel<<<M, 256>>>(hidden, Wg2, bg2, x1, act, out);
}

// round 14
// speedup vs baseline: 1.6768x; 1.1041x over previous
#include <cuda_runtime.h>
#include <cuda_fp16.h>
#include <math.h>
#include <stdint.h>

#define Bsz 4
#define Tt  1024
#define Dm  1024
#define Hh  16
#define HD  64
#define DE  64
#define NT  8
#define NR  64
#define NHH 4
#define NA  2

typedef __half half_t;

// ---------------- scratch (device globals; no allocation allowed) ----------------
__device__ float g_x1    [Bsz*Tt*Dm];
__device__ float g_ax    [Bsz*Hh*Tt];
__device__ float g_evt   [Bsz*Tt*128];   // [t][0:64]=events, [64:72]=tlog
__device__ float g_pn    [NR*DE];
__device__ float g_Y0    [Bsz*Tt*Dm];
__device__ float g_Y1    [Bsz*Tt*Dm];
__device__ float g_wA    [Bsz*Tt*NA];
__device__ float g_ent   [Bsz*Tt];
__device__ float g_hidden[Bsz*Tt*Dm];
__device__ float g_act   [Bsz*Tt*Dm];
// fp16 activations
__device__ half_t g_xh  [Bsz*Tt*Dm];
__device__ half_t g_ndh [Bsz*Tt*Dm];   // nodes fp16
__device__ half_t g_vlh [Bsz*Tt*Dm];   // values fp16
__device__ half_t g_aoh [Bsz*Tt*Dm];
__device__ half_t g_x1h [Bsz*Tt*Dm];
__device__ half_t g_acth[Bsz*Tt*Dm];
// fp16 transposed weights [N][K]
__device__ half_t g_wnt [Dm*Dm];
__device__ half_t g_wvt [Dm*Dm];
__device__ half_t g_wot [Dm*Dm];
__device__ half_t g_wa0t[Dm*Dm];
__device__ half_t g_wa1t[Dm*Dm];
__device__ half_t g_wgt [Dm*2048];
__device__ half_t g_wet [128*Dm];

// ---------------- small helpers ----------------
__device__ __forceinline__ float ex2(float x) {
    float r; asm("ex2.approx.f32 %0,%1;" : "=f"(r) : "f"(x)); return r;
}
__device__ __forceinline__ void mma_f16(float* c, const unsigned* a, const unsigned* b) {
    asm volatile(
        "mma.sync.aligned.m16n8k16.row.col.f32.f16.f16.f32 "
        "{%0,%1,%2,%3},{%4,%5,%6,%7},{%8,%9},{%0,%1,%2,%3};"
        : "+f"(c[0]), "+f"(c[1]), "+f"(c[2]), "+f"(c[3])
        : "r"(a[0]), "r"(a[1]), "r"(a[2]), "r"(a[3]), "r"(b[0]), "r"(b[1]));
}
__device__ __forceinline__ void ldmx4(unsigned& r0, unsigned& r1, unsigned& r2, unsigned& r3,
                                      unsigned addr) {
    asm volatile("ldmatrix.sync.aligned.m8n8.x4.shared.b16 {%0,%1,%2,%3}, [%4];"
                 : "=r"(r0), "=r"(r1), "=r"(r2), "=r"(r3) : "r"(addr));
}
__device__ __forceinline__ float sigpoly(float a) {
    float a2 = a * a;
    return 0.5f + a * (0.25f + a2 * (-0.02083333333f + a2 * 0.002083333333f));
}
__device__ __forceinline__ uint32_t smem_u32(const void* p) {
    uint32_t a;
    asm("{ .reg .u64 t; cvta.to.shared.u64 t, %1; cvt.u32.u64 %0, t; }" : "=r"(a) : "l"(p));
    return a;
}
__device__ __forceinline__ unsigned packh2(float a, float b) {
    __half2 h = __floats2half2_rn(a, b);
    return *(unsigned*)&h;
}

// ================= fp16 tensor-core GEMM with ldmatrix fragments =================
// modes: 0 plain fp32; 1 +addMat + fp16 copy; 3 gate; 4 fp32 w/ ldc; 5 fp16-only out.
// occ 1 by regs (NO minBlocks bound — occ=2 spills accumulators; R12 regression).
#define HSTG 16384
#define HB_OFF 8192
#define HG_SMEM (3*HSTG)

__global__ void __launch_bounds__(256) hgemm(
    const half_t* __restrict__ A, const half_t* __restrict__ A2,
    const half_t* __restrict__ B0, const half_t* __restrict__ B1,
    float* __restrict__ C0, float* __restrict__ C1,
    half_t* __restrict__ Ch, half_t* __restrict__ Ch2,
    const float* __restrict__ addMat, const float* __restrict__ bias,
    const float* __restrict__ entv, const float* __restrict__ wlast,
    int Ktot, int mode, int nbx, int ldc)
{
    extern __shared__ char hsm[];
    const uint32_t smb = smem_u32(hsm);
    const int tid = threadIdx.x, lane = tid & 31, warp = tid >> 5;
    const int g = lane >> 2, tg = lane & 3;
    const int wr = warp >> 2, wc = warp & 3;
    const int mat = blockIdx.x / nbx, cb = blockIdx.x % nbx;
    const int row0 = blockIdx.y * 128, col0 = cb * 128;
    const half_t* B = mat ? B1 : B0;
    float* C = mat ? C1 : C0;
    half_t* Chm = mat ? Ch2 : Ch;

    float acc[4][4][4];
    #pragma unroll
    for (int mt = 0; mt < 4; mt++)
        #pragma unroll
        for (int nt = 0; nt < 4; nt++)
            #pragma unroll
            for (int i = 0; i < 4; i++) acc[mt][nt][i] = 0.f;

    unsigned A_pre[4];
    {
        int lane15 = lane & 15;
        unsigned klaneA = (lane & 16) ? 16u : 0u;
        #pragma unroll
        for (int mt = 0; mt < 4; mt++) {
            int row = wr*64 + mt*16 + lane15;
            unsigned swr = ((row >> 1) & 3) << 4;
            A_pre[mt] = (unsigned)(row*64) + (klaneA ^ swr);
        }
    }
    unsigned B_pre[2];
    {
        unsigned klaneB = (lane & 8) ? 16u : 0u;
        int nbase = wc*32 + ((lane & 16) ? 8 : 0) + (lane & 7);
        #pragma unroll
        for (int ntp = 0; ntp < 2; ntp++) {
            int n = nbase + ntp*16;
            unsigned swn = ((n >> 1) & 3) << 4;
            B_pre[ntp] = (unsigned)(HB_OFF + n*64) + (klaneB ^ swn);
        }
    }

    const int rc = tid >> 2, qc = tid & 3;
    const int ktiles = Ktot / 32;

#define HLOAD(kt, st) do {                                                         \
        int kb_ = (kt) * 32;                                                       \
        const half_t* As_; int ac_;                                                \
        if (kb_ < 1024) { As_ = A; ac_ = kb_; } else { As_ = A2; ac_ = kb_ - 1024; } \
        uint32_t ab_ = smb + (st)*HSTG;                                            \
        uint32_t bb_ = ab_ + HB_OFF;                                               \
        _Pragma("unroll")                                                          \
        for (int i_ = 0; i_ < 2; i_++) {                                           \
            int r_ = rc + i_*64;                                                   \
            uint32_t sw_ = (uint32_t)(((r_ >> 1) & 3) << 4);                       \
            uint32_t co_ = ((uint32_t)(qc*16)) ^ sw_;                              \
            asm volatile("cp.async.ca.shared.global [%0],[%1],16;"                 \
                :: "r"(ab_ + r_*64 + co_),                                         \
                   "l"(As_ + (size_t)(row0 + r_)*1024 + ac_ + qc*8));              \
            asm volatile("cp.async.ca.shared.global [%0],[%1],16;"                 \
                :: "r"(bb_ + r_*64 + co_),                                         \
                   "l"(B + (size_t)(col0 + r_)*Ktot + kb_ + qc*8));                \
        }                                                                          \
        asm volatile("cp.async.commit_group;");                                    \
    } while (0)

    HLOAD(0, 0);
    HLOAD(1, 1);
    HLOAD(2, 2);

    for (int kt = 0; kt < ktiles; kt++) {
        int st = kt % 3;
        if (kt + 2 < ktiles)      asm volatile("cp.async.wait_group 2;");
        else if (kt + 1 < ktiles) asm volatile("cp.async.wait_group 1;");
        else                      asm volatile("cp.async.wait_group 0;");
        __syncthreads();

        const unsigned sbu = smb + st*HSTG;
        #pragma unroll
        for (unsigned kx = 0; kx < 64; kx += 32) {
            unsigned af[4][4], bfr[4][2];
            #pragma unroll
            for (int mt = 0; mt < 4; mt++)
                ldmx4(af[mt][0], af[mt][1], af[mt][2], af[mt][3],
                      sbu + (A_pre[mt] ^ kx));
            #pragma unroll
            for (int ntp = 0; ntp < 2; ntp++)
                ldmx4(bfr[2*ntp][0], bfr[2*ntp][1], bfr[2*ntp+1][0], bfr[2*ntp+1][1],
                      sbu + (B_pre[ntp] ^ kx));
            #pragma unroll
            for (int mt = 0; mt < 4; mt++)
                #pragma unroll
                for (int nt = 0; nt < 4; nt++)
                    mma_f16(acc[mt][nt], af[mt], bfr[nt]);
        }
        __syncthreads();
        if (kt + 3 < ktiles) HLOAD(kt + 3, st);
    }
#undef HLOAD

    #pragma unroll
    for (int mt = 0; mt < 4; mt++) {
        int r = row0 + wr*64 + mt*16 + g;
        float e0v = 0.f, e1v = 0.f;
        if (mode == 3) { e0v = entv[r]; e1v = entv[r + 8]; }
        #pragma unroll
        for (int nt = 0; nt < 4; nt++) {
            int c = col0 + wc*32 + nt*8 + 2*tg;
            float2 v0 = make_float2(acc[mt][nt][0], acc[mt][nt][1]);
            float2 v1 = make_float2(acc[mt][nt][2], acc[mt][nt][3]);
            if (mode == 1) {
                float2 a0 = *(const float2*)&addMat[(size_t)r * 1024 + c];
                float2 a1 = *(const float2*)&addMat[(size_t)(r + 8) * 1024 + c];
                v0.x += a0.x; v0.y += a0.y; v1.x += a1.x; v1.y += a1.y;
            } else if (mode == 3) {
                float2 bb = *(const float2*)&bias[c];
                float2 wl = *(const float2*)&wlast[c];
                v0.x += bb.x + e0v * wl.x; v0.y += bb.y + e0v * wl.y;
                v1.x += bb.x + e1v * wl.x; v1.y += bb.y + e1v * wl.y;
                v0.x = v0.x / (1.f + __expf(-v0.x));
                v0.y = v0.y / (1.f + __expf(-v0.y));
                v1.x = v1.x / (1.f + __expf(-v1.x));
                v1.y = v1.y / (1.f + __expf(-v1.y));
            }
            if (mode == 5) {
                *(unsigned*)(Chm + (size_t)r * 1024 + c)       = packh2(v0.x, v0.y);
                *(unsigned*)(Chm + (size_t)(r + 8) * 1024 + c) = packh2(v1.x, v1.y);
            } else {
                *(float2*)&C[(size_t)r * ldc + c] = v0;
                *(float2*)&C[(size_t)(r + 8) * ldc + c] = v1;
                if (mode == 1) {
                    *(unsigned*)(Ch + (size_t)r * 1024 + c)       = packh2(v0.x, v0.y);
                    *(unsigned*)(Ch + (size_t)(r + 8) * 1024 + c) = packh2(v1.x, v1.y);
                }
            }
        }
    }
}

// ---------------- fp32 -> fp16 convert ----------------
__global__ void to_half(const float* __restrict__ X, half_t* __restrict__ H, int n2)
{
    for (int i = blockIdx.x * blockDim.x + threadIdx.x; i < n2; i += gridDim.x * blockDim.x) {
        float2 v = ((const float2*)X)[i];
        ((unsigned*)H)[i] = packh2(v.x, v.y);
    }
}

// ---------------- all weight transposes in one launch ----------------
__global__ void wtrans_all(
    const float* __restrict__ wn, const float* __restrict__ wv, const float* __restrict__ wo,
    const float* __restrict__ wa, const float* __restrict__ wg,
    const float* __restrict__ we, const float* __restrict__ wt,
    half_t* __restrict__ tn, half_t* __restrict__ tv, half_t* __restrict__ to2,
    half_t* __restrict__ ta0, half_t* __restrict__ ta1, half_t* __restrict__ tg2,
    half_t* __restrict__ te)
{
    __shared__ float t[32][33];
    const int z = blockIdx.z;
    int tx = threadIdx.x, ty = threadIdx.y;
    int k0 = blockIdx.y * 32, n0 = blockIdx.x * 32;

    if (z == 6) {
        if (n0 >= 128 || k0 >= 1024) return;
        #pragma unroll
        for (int i = 0; i < 4; i++) {
            int kk = k0 + ty + 8*i;
            int col = n0 + tx;
            float v;
            if (col < 64)       v = we[(size_t)kk * 64 + col];
            else if (col < 72)  v = wt[(size_t)kk * 8 + (col - 64)];
            else                v = 0.f;
            t[ty + 8*i][tx] = v;
        }
        __syncthreads();
        #pragma unroll
        for (int i = 0; i < 4; i++) {
            int nn = ty + 8*i, kk = tx;
            te[(size_t)(n0 + nn) * 1024 + k0 + kk] = __float2half(t[kk][nn]);
        }
        return;
    }

    const float* W; half_t* T; int K = 1024;
    if      (z == 0) { W = wn; T = tn; }
    else if (z == 1) { W = wv; T = tv; }
    else if (z == 2) { W = wo; T = to2; }
    else if (z == 3) { W = wa; T = ta0; }
    else if (z == 4) { W = wa + 1024*1024; T = ta1; }
    else             { W = wg; T = tg2; K = 2048; }
    if (k0 >= K) return;
    #pragma unroll
    for (int i = 0; i < 4; i++)
        t[ty + 8*i][tx] = W[(size_t)(k0 + ty + 8*i) * 1024 + n0 + tx];
    __syncthreads();
    #pragma unroll
    for (int i = 0; i < 4; i++) {
        int nn = ty + 8*i, kk = tx;
        T[(size_t)(n0 + nn) * K + k0 + kk] = __float2half(t[kk][nn]);
    }
}

// ---------------- ax: one warp per (b,h,t) row, fp16 nodes ----------------
__global__ void ax_kernel(const half_t* __restrict__ ndh,
                          const float* __restrict__ arity_w,
                          float* __restrict__ ax)
{
    int gw = (blockIdx.x * blockDim.x + threadIdx.x) >> 5;
    int lane = threadIdx.x & 31;
    if (gw >= Bsz*Hh*Tt) return;
    int t = gw % Tt, h = (gw / Tt) % Hh, b = gw / (Tt*Hh);
    const unsigned* np = (const unsigned*)(ndh + (size_t)(b*Tt + t)*Dm + h*HD);
    const float2* w  = (const float2*)(arity_w + h*HD);
    unsigned u = np[lane];
    __half2 hv = *(__half2*)&u;
    float2 ww = w[lane];
    float s = __half2float(__low2half(hv))*ww.x + __half2float(__high2half(hv))*ww.y;
    s += __shfl_xor_sync(0xffffffffu, s, 1);
    s += __shfl_xor_sync(0xffffffffu, s, 2);
    s += __shfl_xor_sync(0xffffffffu, s, 4);
    s += __shfl_xor_sync(0xffffffffu, s, 8);
    s += __shfl_xor_sync(0xffffffffu, s, 16);
    if (lane == 0) ax[gw] = s;
}

// ---------------- fp16 flash attention: native fp16 loads, single-precision ------
// smem (bytes): KS[2][64][72]h | VS[2][64][72]h | VT[64][72]h | PH[8][16][72]h | axs
#define KS_OFF 0
#define VS_OFF 18432
#define VT_OFF 36864
#define PH_OFF 46080
#define AX_OFF 64512
#define ATTN_SMEM 65024

__global__ void __launch_bounds__(256) attn_tc(
    const half_t* __restrict__ ndh, const half_t* __restrict__ vlh,
    const float* __restrict__ ax, half_t* __restrict__ outh)
{
    extern __shared__ char smbuf[];
    float* axs = (float*)(smbuf + AX_OFF);

    const int tid = threadIdx.x, lane = tid & 31, warp = tid >> 5;
    const int g = lane >> 2, tg = lane & 3;
    const int qblk = blockIdx.x, h = blockIdx.y, b = blockIdx.z;

    const half_t* nb  = ndh + (size_t)(b*Tt)*Dm + h*HD;
    const half_t* vb  = vlh + (size_t)(b*Tt)*Dm + h*HD;
    const float* axp = ax + (b*Hh + h)*Tt;
    const int t0 = qblk * 128;
    const int r0 = t0 + warp*16 + g;

    half_t* PHw = (half_t*)(smbuf + PH_OFF) + warp * 16 * 72;

    // Q fragments: fp16 straight from global
    unsigned qf[4][4];
    #pragma unroll
    for (int kb = 0; kb < 4; kb++) {
        const half_t* q0 = nb + (size_t)r0*Dm + kb*16;
        const half_t* q1 = nb + (size_t)(r0+8)*Dm + kb*16;
        qf[kb][0] = *(const unsigned*)(q0 + 2*tg);
        qf[kb][1] = *(const unsigned*)(q1 + 2*tg);
        qf[kb][2] = *(const unsigned*)(q0 + 8 + 2*tg);
        qf[kb][3] = *(const unsigned*)(q1 + 8 + 2*tg);
    }
    const float axt0 = axp[r0] * 0.125f;
    const float axt1 = axp[r0+8] * 0.125f;

    float oacc[8][4];
    #pragma unroll
    for (int nt = 0; nt < 8; nt++)
        #pragma unroll
        for (int i = 0; i < 4; i++) oacc[nt][i] = 0.f;
    float m2a = -1e30f, m2b = -1e30f, la = 0.f, lb = 0.f;
    const float SC2 = 0.125f * 1.44269504f;

    unsigned smb = (unsigned)__cvta_generic_to_shared(smbuf);

    // K,V tiles: 64 rows x 128B each = 512 chunks of 16B per tensor; 2/thread.
#define ALOAD(kvt, bf) do {                                                       \
        int s0_ = (kvt) * 64;                                                     \
        _Pragma("unroll")                                                         \
        for (int i = 0; i < 2; i++) {                                             \
            int e = tid + i*256;                                                  \
            int r_ = e >> 3, q_ = e & 7;                                          \
            unsigned kdst = smb + KS_OFF + (bf)*9216 + (r_*72 + q_*8)*2;          \
            unsigned vdst = smb + VS_OFF + (bf)*9216 + (r_*72 + q_*8)*2;          \
            asm volatile("cp.async.ca.shared.global [%0],[%1],16;"                \
                :: "r"(kdst), "l"(nb + (size_t)(s0_+r_)*Dm + q_*8));              \
            asm volatile("cp.async.ca.shared.global [%0],[%1],16;"                \
                :: "r"(vdst), "l"(vb + (size_t)(s0_+r_)*Dm + q_*8));              \
        }                                                                         \
        if (tid < 16) {                                                           \
            unsigned adst = smb + AX_OFF + ((bf)*64 + tid*4)*4;                   \
            asm volatile("cp.async.ca.shared.global [%0],[%1],16;"                \
                :: "r"(adst), "l"(axp + s0_ + tid*4));                            \
        }                                                                         \
        asm volatile("cp.async.commit_group;");                                   \
    } while (0)

    int buf = 0;
    ALOAD(0, 0);
    for (int kvt = 0; kvt < 16; kvt++) {
        if (kvt + 1 < 16) {
            ALOAD(kvt + 1, buf ^ 1);
            asm volatile("cp.async.wait_group 1;");
        } else {
            asm volatile("cp.async.wait_group 0;");
        }
        __syncthreads();

        // transpose V fp16: VS[s][d] -> VT[d][s] (pad 72)
        {
            const half_t* vs = (const half_t*)(smbuf + VS_OFF + buf*9216);
            half_t* vt = (half_t*)(smbuf + VT_OFF);
            #pragma unroll
            for (int i = 0; i < 8; i++) {
                int e = tid + i*256;
                int d_ = e & 63, sp = e >> 6;
                unsigned short u0 = *(const unsigned short*)&vs[(2*sp)*72 + d_];
                unsigned short u1 = *(const unsigned short*)&vs[(2*sp+1)*72 + d_];
                *(unsigned*)(vt + d_*72 + 2*sp) = ((unsigned)u1 << 16) | u0;
            }
        }
        __syncthreads();

        // ---- S = Q K^T (single fp16) ----
        const half_t* KH = (const half_t*)(smbuf + KS_OFF + buf*9216);
        float sacc[8][4];
        #pragma unroll
        for (int nt = 0; nt < 8; nt++)
            #pragma unroll
            for (int i = 0; i < 4; i++) sacc[nt][i] = 0.f;
        #pragma unroll
        for (int kb = 0; kb < 4; kb++) {
            #pragma unroll
            for (int nt = 0; nt < 8; nt++) {
                const half_t* kr = KH + (nt*8 + g)*72 + kb*16;
                unsigned bfr[2];
                bfr[0] = *(const unsigned*)(kr + 2*tg);
                bfr[1] = *(const unsigned*)(kr + 8 + 2*tg);
                mma_f16(sacc[nt], qf[kb], bfr);
            }
        }

        float tm0 = -1e30f, tm1 = -1e30f;
        #pragma unroll
        for (int nt = 0; nt < 8; nt++) {
            float ax0 = axs[buf*64 + nt*8 + 2*tg] * 0.125f;
            float ax1 = axs[buf*64 + nt*8 + 2*tg + 1] * 0.125f;
            sacc[nt][0] *= sigpoly(axt0 + ax0) * SC2;
            sacc[nt][1] *= sigpoly(axt0 + ax1) * SC2;
            sacc[nt][2] *= sigpoly(axt1 + ax0) * SC2;
            sacc[nt][3] *= sigpoly(axt1 + ax1) * SC2;
            tm0 = fmaxf(tm0, fmaxf(sacc[nt][0], sacc[nt][1]));
            tm1 = fmaxf(tm1, fmaxf(sacc[nt][2], sacc[nt][3]));
        }
        tm0 = fmaxf(tm0, __shfl_xor_sync(0xffffffffu, tm0, 1));
        tm0 = fmaxf(tm0, __shfl_xor_sync(0xffffffffu, tm0, 2));
        tm1 = fmaxf(tm1, __shfl_xor_sync(0xffffffffu, tm1, 1));
        tm1 = fmaxf(tm1, __shfl_xor_sync(0xffffffffu, tm1, 2));

        float mn0 = fmaxf(m2a, tm0), mn1 = fmaxf(m2b, tm1);
        float cr0 = ex2(m2a - mn0), cr1 = ex2(m2b - mn1);
        la *= cr0; lb *= cr1;
        #pragma unroll
        for (int nt = 0; nt < 8; nt++) {
            oacc[nt][0] *= cr0; oacc[nt][1] *= cr0;
            oacc[nt][2] *= cr1; oacc[nt][3] *= cr1;
        }
        m2a = mn0; m2b = mn1;

        // ---- P = exp2(sc - mn), single fp16 ----
        #pragma unroll
        for (int nt = 0; nt < 8; nt++) {
            float p00 = ex2(sacc[nt][0] - mn0);
            float p01 = ex2(sacc[nt][1] - mn0);
            float p10 = ex2(sacc[nt][2] - mn1);
            float p11 = ex2(sacc[nt][3] - mn1);
            la += p00 + p01; lb += p10 + p11;
            *(unsigned*)(PHw + g*72 + nt*8 + 2*tg)     = packh2(p00, p01);
            *(unsigned*)(PHw + (g+8)*72 + nt*8 + 2*tg) = packh2(p10, p11);
        }
        __syncwarp();

        // ---- O += P V^T (single fp16) ----
        const half_t* VT = (const half_t*)(smbuf + VT_OFF);
        #pragma unroll
        for (int kb = 0; kb < 4; kb++) {
            unsigned ph[4];
            ph[0] = *(const unsigned*)(PHw + g*72 + kb*16 + 2*tg);
            ph[1] = *(const unsigned*)(PHw + (g+8)*72 + kb*16 + 2*tg);
            ph[2] = *(const unsigned*)(PHw + g*72 + kb*16 + 8 + 2*tg);
            ph[3] = *(const unsigned*)(PHw + (g+8)*72 + kb*16 + 8 + 2*tg);
            #pragma unroll
            for (int nt = 0; nt < 8; nt++) {
                const half_t* vr = VT + (nt*8 + g)*72 + kb*16;
                unsigned vf[2];
                vf[0] = *(const unsigned*)(vr + 2*tg);
                vf[1] = *(const unsigned*)(vr + 8 + 2*tg);
                mma_f16(oacc[nt], ph, vf);
            }
        }
        __syncthreads();   // everyone done with KS/VS(buf) + VT before overwrite
        buf ^= 1;
    }
#undef ALOAD

    la += __shfl_xor_sync(0xffffffffu, la, 1);
    la += __shfl_xor_sync(0xffffffffu, la, 2);
    lb += __shfl_xor_sync(0xffffffffu, lb, 1);
    lb += __shfl_xor_sync(0xffffffffu, lb, 2);
    float i0 = 1.f / la, i1 = 1.f / lb;
    size_t o0 = (size_t)(b*Tt + r0)*Dm + h*HD;
    size_t o1 = (size_t)(b*Tt + r0 + 8)*Dm + h*HD;
    #pragma unroll
    for (int nt = 0; nt < 8; nt++) {
        *(unsigned*)(outh + o0 + nt*8 + 2*tg) = packh2(oacc[nt][0]*i0, oacc[nt][1]*i0);
        *(unsigned*)(outh + o1 + nt*8 + 2*tg) = packh2(oacc[nt][2]*i1, oacc[nt][3]*i1);
    }
}

// ---------------- normalized patterns ----------------
__global__ void pn_kernel(const float* __restrict__ patterns, float* __restrict__ pn)
{
    int r = threadIdx.x;
    float s = 0.f;
    #pragma unroll
    for (int d = 0; d < DE; d++) { float v = patterns[r*DE + d]; s += v*v; }
    float inv = 1.f / fmaxf(sqrtf(s), 1e-12f);
    #pragma unroll
    for (int d = 0; d < DE; d++) pn[r*DE + d] = patterns[r*DE + d] * inv;
}

// ---------------- per-token rule bank + entropy ----------------
__global__ void token_kernel(
    const float* __restrict__ evt,
    const float* __restrict__ patterns, const float* __restrict__ pn,
    const float* __restrict__ W_alt, const float* __restrict__ log_temp,
    float* __restrict__ wA, float* __restrict__ entn)
{
    const int t = blockIdx.x;
    const int tid = threadIdx.x;
    __shared__ float en[64], sims[64], red[64], wp[64];
    __shared__ float sh_hw[4]; __shared__ int sh_idx[4];
    __shared__ float sh_misc[2];

    float e = evt[(size_t)t*128 + tid];
    red[tid] = e*e;
    __syncthreads();
    for (int off = 32; off > 0; off >>= 1) {
        if (tid < off) red[tid] += red[tid + off];
        __syncthreads();
    }
    float nrm = fmaxf(sqrtf(red[0]), 1e-12f);
    en[tid] = e / nrm;
    __syncthreads();

    float s = 0.f;
    #pragma unroll
    for (int d = 0; d < DE; d++) s += en[d] * pn[tid*DE + d];
    sims[tid] = s;
    __syncthreads();

    if (tid == 0) {
        float temp = expf(log_temp[0]);
        temp = fminf(fmaxf(temp, 0.01f), 10.f);
        float loc[NR];
        for (int r = 0; r < NR; r++) loc[r] = sims[r];
        float vals[NHH]; int idx[NHH];
        for (int k = 0; k < NHH; k++) {
            float best = -1e30f; int bi = 0;
            for (int r = 0; r < NR; r++)
                if (loc[r] > best) { best = loc[r]; bi = r; }
            vals[k] = best; idx[k] = bi; loc[bi] = -1e30f;
        }
        float sum = 0.f, w[NHH];
        for (int k = 0; k < NHH; k++) { w[k] = expf((vals[k] - vals[0]) / temp); sum += w[k]; }
        for (int k = 0; k < NHH; k++) { sh_hw[k] = w[k] / sum; sh_idx[k] = idx[k]; }
        sh_misc[0] = 1.f / (1.f + expf(-vals[0]));
        sh_misc[1] = temp;
    }
    __syncthreads();

    float wpv = 0.f;
    #pragma unroll
    for (int k = 0; k < NHH; k++) wpv += sh_hw[k] * patterns[sh_idx[k]*DE + tid];
    wp[tid] = wpv;
    __syncthreads();

    if (tid == 0) {
        float temp = sh_misc[1], sig = sh_misc[0];
        float l0 = 0.f, l1 = 0.f;
        for (int d = 0; d < DE; d++) { l0 += wp[d]*W_alt[d*NA]; l1 += wp[d]*W_alt[d*NA + 1]; }
        l0 /= temp; l1 /= temp;
        float mx = fmaxf(l0, l1);
        float e0 = expf(l0 - mx), e1 = expf(l1 - mx);
        float inv = 1.f / (e0 + e1);
        wA[t*NA]     = e0*inv*sig;
        wA[t*NA + 1] = e1*inv*sig;

        const float* tl = evt + (size_t)t*128 + 64;
        float m8 = -1e30f;
        for (int j = 0; j < NT; j++) m8 = fmaxf(m8, tl[j]);
        float se = 0.f, pz[NT];
        for (int j = 0; j < NT; j++) { pz[j] = expf(tl[j] - m8); se += pz[j]; }
        float ent = 0.f;
        for (int j = 0; j < NT; j++) {
            float p = pz[j] / se;
            ent -= p * logf(p + 1e-10f);
        }
        entn[t] = ent / logf((float)NT);
    }
}

// ---------------- combine: actions_out fp32 + fp16 ----------------
__global__ void combine_kernel(
    const float* __restrict__ Y0, const float* __restrict__ Y1,
    const float* __restrict__ wA,
    float* __restrict__ act, half_t* __restrict__ acth)
{
    const int t = blockIdx.x;
    const float w0 = wA[t*NA], w1 = wA[t*NA + 1];
    for (int c = threadIdx.x; c < Dm/2; c += blockDim.x) {
        size_t i = (size_t)t*(Dm/2) + c;
        float2 y0 = ((const float2*)Y0)[i];
        float2 y1 = ((const float2*)Y1)[i];
        float a0 = w0*y0.x + w1*y1.x;
        float a1 = w0*y0.y + w1*y1.y;
        ((float2*)act)[i] = make_float2(a0, a1);
        ((unsigned*)acth)[i] = packh2(a0, a1);
    }
}

// ---------------- gate scalar + final output ----------------
__global__ void final_kernel(
    const float* __restrict__ hidden, const float* __restrict__ Wg2,
    const float* __restrict__ bg2, const float* __restrict__ x1,
    const float* __restrict__ act, float* __restrict__ out)
{
    const int t = blockIdx.x;
    __shared__ float red[256];
    float s = 0.f;
    for (int c = threadIdx.x; c < Dm; c += 256)
        s += hidden[(size_t)t*Dm + c] * Wg2[c];
    red[threadIdx.x] = s;
    __syncthreads();
    for (int off = 128; off > 0; off >>= 1) {
        if (threadIdx.x < off) red[threadIdx.x] += red[threadIdx.x + off];
        __syncthreads();
    }
    float g = 1.f / (1.f + expf(-(red[0] + bg2[0])));
    for (int c = threadIdx.x; c < Dm; c += 256) {
        size_t i = (size_t)t*Dm + c;
        out[i] = x1[i] + g*act[i];
    }
}

// ---------------- host launcher ----------------
extern "C" void kernel_launch(void* const* d_in, const int* in_sizes, int n_in,
                              void* d_out, int out_size)
{
    const float* x        = (const float*)d_in[0];
    const float* W_node   = (const float*)d_in[1];
    const float* W_value  = (const float*)d_in[2];
    const float* W_out    = (const float*)d_in[3];
    const float* arity_w  = (const float*)d_in[4];
    const float* W_event  = (const float*)d_in[5];
    const float* W_type   = (const float*)d_in[6];
    const float* patterns = (const float*)d_in[7];
    const float* W_actions= (const float*)d_in[8];
    const float* W_alt    = (const float*)d_in[9];
    const float* log_temp = (const float*)d_in[10];
    const float* Wg1      = (const float*)d_in[11];
    const float* bg1      = (const float*)d_in[12];
    const float* Wg2      = (const float*)d_in[13];
    const float* bg2      = (const float*)d_in[14];
    float* out = (float*)d_out;

    float *x1, *ax, *evt, *pn, *Y0, *Y1, *wA, *ent, *hidden, *act;
    half_t *xh, *ndh, *vlh, *aoh, *x1h, *acth, *wnt, *wvt, *wot, *wa0t, *wa1t, *wgt, *wet;
    cudaGetSymbolAddress((void**)&x1,     g_x1);
    cudaGetSymbolAddress((void**)&ax,     g_ax);
    cudaGetSymbolAddress((void**)&evt,    g_evt);
    cudaGetSymbolAddress((void**)&pn,     g_pn);
    cudaGetSymbolAddress((void**)&Y0,     g_Y0);
    cudaGetSymbolAddress((void**)&Y1,     g_Y1);
    cudaGetSymbolAddress((void**)&wA,     g_wA);
    cudaGetSymbolAddress((void**)&ent,    g_ent);
    cudaGetSymbolAddress((void**)&hidden, g_hidden);
    cudaGetSymbolAddress((void**)&act,    g_act);
    cudaGetSymbolAddress((void**)&xh,   g_xh);
    cudaGetSymbolAddress((void**)&ndh,  g_ndh);
    cudaGetSymbolAddress((void**)&vlh,  g_vlh);
    cudaGetSymbolAddress((void**)&aoh,  g_aoh);
    cudaGetSymbolAddress((void**)&x1h,  g_x1h);
    cudaGetSymbolAddress((void**)&acth, g_acth);
    cudaGetSymbolAddress((void**)&wnt,  g_wnt);
    cudaGetSymbolAddress((void**)&wvt,  g_wvt);
    cudaGetSymbolAddress((void**)&wot,  g_wot);
    cudaGetSymbolAddress((void**)&wa0t, g_wa0t);
    cudaGetSymbolAddress((void**)&wa1t, g_wa1t);
    cudaGetSymbolAddress((void**)&wgt,  g_wgt);
    cudaGetSymbolAddress((void**)&wet,  g_wet);

    cudaFuncSetAttribute(attn_tc, cudaFuncAttributeMaxDynamicSharedMemorySize, ATTN_SMEM);
    cudaFuncSetAttribute(hgemm,   cudaFuncAttributeMaxDynamicSharedMemorySize, HG_SMEM);

    const int M = Bsz*Tt;

    to_half<<<256, 256>>>(x, xh, M*Dm/2);
    wtrans_all<<<dim3(32, 64, 7), dim3(32, 8)>>>(W_node, W_value, W_out, W_actions, Wg1,
                                                 W_event, W_type,
                                                 wnt, wvt, wot, wa0t, wa1t, wgt, wet);

    // node | value -> fp16 only (mode 5)
    hgemm<<<dim3(16, 32), 256, HG_SMEM>>>(xh, nullptr, wnt, wvt, nullptr, nullptr,
        ndh, vlh, nullptr, nullptr, nullptr, nullptr, 1024, 5, 8, 1024);
    ax_kernel<<<(Bsz*Hh*Tt*32 + 255)/256, 256>>>(ndh, arity_w, ax);
    attn_tc<<<dim3(Tt/128, Hh, Bsz), 256, ATTN_SMEM>>>(ndh, vlh, ax, aoh);
    // x1 = x + attn_out @ W_out
    hgemm<<<dim3(8, 32), 256, HG_SMEM>>>(aoh, nullptr, wot, nullptr, x1, nullptr,
        x1h, nullptr, x, nullptr, nullptr, nullptr, 1024, 1, 8, 1024);
    // events|tlog
    hgemm<<<dim3(1, 32), 256, HG_SMEM>>>(x1h, nullptr, wet, nullptr, evt, nullptr,
        nullptr, nullptr, nullptr, nullptr, nullptr, nullptr, 1024, 4, 1, 128);
    // Y0 | Y1
    hgemm<<<dim3(16, 32), 256, HG_SMEM>>>(x1h, nullptr, wa0t, wa1t, Y0, Y1,
        nullptr, nullptr, nullptr, nullptr, nullptr, nullptr, 1024, 0, 8, 1024);
    pn_kernel<<<1, 64>>>(patterns, pn);
    token_kernel<<<M, 64>>>(evt, patterns, pn, W_alt, log_temp, wA, ent);
    combine_kernel<<<M, 256>>>(Y0, Y1, wA, act, acth);
    // gate
    hgemm<<<dim3(8, 32), 256, HG_SMEM>>>(x1h, acth, wgt, nullptr, hidden, nullptr,
        nullptr, nullptr, nullptr, bg1, ent, Wg1 + (size_t)2048*1024, 2048, 3, 8, 1024);
    final_kernel<<<M, 256>>>(hidden, Wg2, bg2, x1, act, out);
}